// round 3
// baseline (speedup 1.0000x reference)
#include <cuda_runtime.h>
#include <math.h>

// Problem constants
#define H48   48
#define NG    8
#define NC    64
#define NB    2304        // W*D = 48*48
#define NHWD  110592      // H*W*D
#define NOC   256         // 192 kv channels + 64 q channels
#define RELW  95          // 2*K-1
#define EPSV  1e-5f

// ---------------- scratch (device globals; no allocations) ----------------
__device__ float d_proj[NOC * NHWD];        // [o][b*48 + h]   113 MB
__device__ float d_outpre[NB * NOC * H48];  // [b][o*48 + h]   113 MB
__device__ float d_psum[NOC], d_psq[NOC], d_pscale[NOC], d_pshift[NOC];
__device__ float d_ssum[24],  d_ssq[24],  d_sscale[24],  d_sshift[24];
__device__ float d_osum[NOC], d_osq[NOC], d_oscale[NOC], d_oshift[NOC];

// ---------------- init: zero stat accumulators each launch ----------------
__global__ void k_init() {
    int t = threadIdx.x;
    if (t < NOC) { d_psum[t] = 0.f; d_psq[t] = 0.f; d_osum[t] = 0.f; d_osq[t] = 0.f; }
    if (t < 24)  { d_ssum[t] = 0.f; d_ssq[t]  = 0.f; }
}

// ---------------- pass 1: projection GEMM + per-channel stats --------------
// out[o][b][h] = sum_c W[o][c] * x[c][h][b],  b = w*48+d
// Block: all 256 channels x (8 b x 8 h) spatial tile. 256 threads.
// Thread (og, bl): 8 channels (og*8+i) x 8 h values at fixed b. float4 stores.
__global__ void k_proj(const float* __restrict__ x,
                       const float* __restrict__ Wkv,
                       const float* __restrict__ Wq) {
    extern __shared__ float sm[];
    float* Ws = sm;              // 256 x 65 (padded)
    float* Xs = sm + 256 * 65;   // 64 x 64 : [c][hl*8+bl]
    int tid = threadIdx.x;
    int bt = blockIdx.x % 288, ht = blockIdx.x / 288;
    int b0 = bt * 8, h0 = ht * 8;

    for (int idx = tid; idx < 256 * 64; idx += 256) {
        int o = idx >> 6, c = idx & 63;
        Ws[o * 65 + c] = (o < 192) ? Wkv[o * 64 + c] : Wq[(o - 192) * 64 + c];
    }
    #pragma unroll
    for (int t = 0; t < 16; t++) {
        int idx = t * 256 + tid;
        int c = idx >> 6, sp = idx & 63;
        int hl = sp >> 3, bl = sp & 7;
        Xs[c * 64 + sp] = x[c * NHWD + (h0 + hl) * 2304 + b0 + bl];
    }
    __syncthreads();

    int og = tid >> 3, bl = tid & 7;
    float acc[8][8];
    #pragma unroll
    for (int i = 0; i < 8; i++)
        #pragma unroll
        for (int h = 0; h < 8; h++) acc[i][h] = 0.f;

    #pragma unroll 4
    for (int c = 0; c < 64; c++) {
        float xv[8];
        #pragma unroll
        for (int hl = 0; hl < 8; hl++) xv[hl] = Xs[c * 64 + hl * 8 + bl];
        #pragma unroll
        for (int i = 0; i < 8; i++) {
            float wv = Ws[(og * 8 + i) * 65 + c];
            #pragma unroll
            for (int hl = 0; hl < 8; hl++) acc[i][hl] = fmaf(wv, xv[hl], acc[i][hl]);
        }
    }

    #pragma unroll
    for (int i = 0; i < 8; i++) {
        int o = og * 8 + i;
        float s = 0.f, q = 0.f;
        #pragma unroll
        for (int hl = 0; hl < 8; hl++) { float v = acc[i][hl]; s += v; q += v * v; }
        float* base = d_proj + o * NHWD + (b0 + bl) * 48 + h0;
        *(float4*)(base)     = make_float4(acc[i][0], acc[i][1], acc[i][2], acc[i][3]);
        *(float4*)(base + 4) = make_float4(acc[i][4], acc[i][5], acc[i][6], acc[i][7]);
        s += __shfl_down_sync(0xffffffffu, s, 4, 8);
        s += __shfl_down_sync(0xffffffffu, s, 2, 8);
        s += __shfl_down_sync(0xffffffffu, s, 1, 8);
        q += __shfl_down_sync(0xffffffffu, q, 4, 8);
        q += __shfl_down_sync(0xffffffffu, q, 2, 8);
        q += __shfl_down_sync(0xffffffffu, q, 1, 8);
        if (bl == 0) { atomicAdd(&d_psum[o], s); atomicAdd(&d_psq[o], q); }
    }
}

__global__ void k_fin_proj(const float* __restrict__ gkv, const float* __restrict__ bkv,
                           const float* __restrict__ gq,  const float* __restrict__ bq) {
    int o = threadIdx.x;
    float n = 110592.0f;
    float m = d_psum[o] / n;
    float var = d_psq[o] / n - m * m;
    float g = (o < 192) ? gkv[o] : gq[o - 192];
    float bb = (o < 192) ? bkv[o] : bq[o - 192];
    float sc = rsqrtf(var + EPSV) * g;
    d_pscale[o] = sc;
    d_pshift[o] = bb - m * sc;
}

// ------------- shared logit micro-kernel: 3i x 6j tile, c-loop unrolled ----
__device__ __forceinline__ void compute_logits(const float (*qs)[48], const float (*ks)[48],
                                               const float (*rl)[96], int i0, int j0,
                                               float* A, float* Bq, float* Ck) {
    #pragma unroll
    for (int e = 0; e < 18; e++) { A[e] = 0.f; Bq[e] = 0.f; Ck[e] = 0.f; }
    #pragma unroll
    for (int c = 0; c < 8; c++) {
        float qv[3], kv[6], rq[8], rk[8];
        #pragma unroll
        for (int di = 0; di < 3; di++) qv[di] = qs[c][i0 + di];
        #pragma unroll
        for (int dj = 0; dj < 6; dj++) kv[dj] = ks[c][j0 + dj];
        const float* rqp = &rl[c][0]     + (i0 - j0 + 42);  // d = i-j+47
        const float* rkp = &rl[8 + c][0] + (j0 - i0 + 45);  // d = j-i+47
        #pragma unroll
        for (int t = 0; t < 8; t++) { rq[t] = rqp[t]; rk[t] = rkp[t]; }
        #pragma unroll
        for (int di = 0; di < 3; di++)
            #pragma unroll
            for (int dj = 0; dj < 6; dj++) {
                int e = di * 6 + dj;
                A[e]  = fmaf(qv[di], kv[dj],           A[e]);
                Bq[e] = fmaf(qv[di], rq[di + 5 - dj],  Bq[e]);
                Ck[e] = fmaf(kv[dj], rk[dj + 2 - di],  Ck[e]);
            }
    }
}

// ---------------- pass 2: sim BN stats (qk/qr/kr, 24 channels) -------------
__global__ void k_simstat(const float* __restrict__ rel,
                          const float* __restrict__ fqr_p, const float* __restrict__ fkr_p) {
    __shared__ float qs[8][48], ks[8][48], rl[16][96];
    __shared__ float red[24];
    int tid = threadIdx.x;
    int b = blockIdx.x >> 3, g = blockIdx.x & 7;

    for (int idx = tid; idx < 384; idx += 128) {
        int c = idx / 48, h = idx % 48;
        int oq = 192 + g * 8 + c;
        qs[c][h] = d_proj[oq * NHWD + b * 48 + h] * d_pscale[oq] + d_pshift[oq];
        int ok = g * 24 + c;
        ks[c][h] = d_proj[ok * NHWD + b * 48 + h] * d_pscale[ok] + d_pshift[ok];
    }
    for (int idx = tid; idx < 16 * 95; idx += 128)
        rl[idx / 95][idx % 95] = rel[idx];
    __syncthreads();

    float fqr = fqr_p[0], fkr = fkr_p[0];
    int i0 = (tid >> 3) * 3, j0 = (tid & 7) * 6;
    float A[18], Bq[18], Ck[18];
    compute_logits(qs, ks, rl, i0, j0, A, Bq, Ck);

    float st[6] = {0.f, 0.f, 0.f, 0.f, 0.f, 0.f};
    #pragma unroll
    for (int e = 0; e < 18; e++) {
        float a = A[e];        st[0] += a; st[1] += a * a;
        float bb = Bq[e] * fqr; st[2] += bb; st[3] += bb * bb;
        float cc = Ck[e] * fkr; st[4] += cc; st[5] += cc * cc;
    }
    #pragma unroll
    for (int t = 0; t < 6; t++)
        #pragma unroll
        for (int off = 16; off; off >>= 1)
            st[t] += __shfl_xor_sync(0xffffffffu, st[t], off);
    int w = tid >> 5;
    if ((tid & 31) == 0)
        #pragma unroll
        for (int t = 0; t < 6; t++) red[w * 6 + t] = st[t];
    __syncthreads();
    if (tid < 6) {
        float v = red[tid] + red[6 + tid] + red[12 + tid] + red[18 + tid];
        int ch = g + (tid >> 1) * 8;
        if (tid & 1) atomicAdd(&d_ssq[ch], v); else atomicAdd(&d_ssum[ch], v);
    }
}

__global__ void k_fin_sim(const float* __restrict__ gsim, const float* __restrict__ bsim) {
    int t = threadIdx.x;
    if (t < 24) {
        float n = 5308416.0f;   // B*H*H
        float m = d_ssum[t] / n;
        float var = d_ssq[t] / n - m * m;
        float sc = rsqrtf(var + EPSV) * gsim[t];
        d_sscale[t] = sc;
        d_sshift[t] = bsim[t] - m * sc;
    }
}

// ------- pass 3: logits (BN'd, summed) + softmax + sv/sve + out stats ------
__global__ void k_attn(const float* __restrict__ rel,
                       const float* __restrict__ fqr_p, const float* __restrict__ fkr_p,
                       const float* __restrict__ fsv_p, const float* __restrict__ fsve_p) {
    __shared__ float qs[8][48], ks[8][48], vs[16][48], rl[32][96];
    __shared__ float S[48 * 48];
    __shared__ float sst[64];
    int tid = threadIdx.x;
    int b = blockIdx.x >> 3, g = blockIdx.x & 7;
    if (tid < 64) sst[tid] = 0.f;

    for (int idx = tid; idx < 384; idx += 128) {
        int c = idx / 48, h = idx % 48;
        int oq = 192 + g * 8 + c;
        qs[c][h] = d_proj[oq * NHWD + b * 48 + h] * d_pscale[oq] + d_pshift[oq];
        int ok = g * 24 + c;
        ks[c][h] = d_proj[ok * NHWD + b * 48 + h] * d_pscale[ok] + d_pshift[ok];
    }
    for (int idx = tid; idx < 768; idx += 128) {
        int c = idx / 48, h = idx % 48;
        int ov = g * 24 + 8 + c;
        vs[c][h] = d_proj[ov * NHWD + b * 48 + h] * d_pscale[ov] + d_pshift[ov];
    }
    for (int idx = tid; idx < 32 * 95; idx += 128)
        rl[idx / 95][idx % 95] = rel[idx];
    __syncthreads();

    float fqr = fqr_p[0], fkr = fkr_p[0];
    float ca  = d_sscale[g];
    float cb  = d_sscale[8 + g]  * fqr;
    float cc2 = d_sscale[16 + g] * fkr;
    float shc = d_sshift[g] + d_sshift[8 + g] + d_sshift[16 + g];

    // Phase A: BN'd summed logits into shared S
    {
        int i0 = (tid >> 3) * 3, j0 = (tid & 7) * 6;
        float A[18], Bq[18], Ck[18];
        compute_logits(qs, ks, rl, i0, j0, A, Bq, Ck);
        #pragma unroll
        for (int di = 0; di < 3; di++)
            #pragma unroll
            for (int dj = 0; dj < 6; dj++) {
                int e = di * 6 + dj;
                S[(i0 + di) * 48 + (j0 + dj)] = fmaf(A[e], ca, fmaf(Bq[e], cb, fmaf(Ck[e], cc2, shc)));
            }
    }
    __syncthreads();

    // Phase B: softmax over j (one warp per row, 4 warps x 12 rows)
    {
        int w = tid >> 5, lane = tid & 31;
        for (int t = 0; t < 12; t++) {
            int r = w * 12 + t;
            float v0 = S[r * 48 + lane];
            float v1 = (lane < 16) ? S[r * 48 + 32 + lane] : -1e30f;
            float m = fmaxf(v0, v1);
            #pragma unroll
            for (int off = 16; off; off >>= 1) m = fmaxf(m, __shfl_xor_sync(0xffffffffu, m, off));
            float e0 = __expf(v0 - m);
            float e1 = (lane < 16) ? __expf(v1 - m) : 0.f;
            float s = e0 + e1;
            #pragma unroll
            for (int off = 16; off; off >>= 1) s += __shfl_xor_sync(0xffffffffu, s, off);
            float inv = 1.f / s;
            S[r * 48 + lane] = e0 * inv;
            if (lane < 16) S[r * 48 + 32 + lane] = e1 * inv;
        }
    }
    __syncthreads();

    // Phase C: sv + sve; thread tile = 2 channels x 3 rows
    int c0 = (tid & 7) * 2, i0 = (tid >> 3) * 3;
    float svv[2][3] = {{0.f,0.f,0.f},{0.f,0.f,0.f}};
    float sev[2][3] = {{0.f,0.f,0.f},{0.f,0.f,0.f}};
    #pragma unroll 4
    for (int j = 0; j < 48; j++) {
        float s0 = S[i0 * 48 + j], s1 = S[(i0 + 1) * 48 + j], s2 = S[(i0 + 2) * 48 + j];
        float v0 = vs[c0][j], v1 = vs[c0 + 1][j];
        svv[0][0] = fmaf(s0, v0, svv[0][0]);
        svv[0][1] = fmaf(s1, v0, svv[0][1]);
        svv[0][2] = fmaf(s2, v0, svv[0][2]);
        svv[1][0] = fmaf(s0, v1, svv[1][0]);
        svv[1][1] = fmaf(s1, v1, svv[1][1]);
        svv[1][2] = fmaf(s2, v1, svv[1][2]);
        const float* r0 = &rl[16 + c0][0] + (47 - j);
        const float* r1 = &rl[17 + c0][0] + (47 - j);
        sev[0][0] = fmaf(s0, r0[i0],     sev[0][0]);
        sev[0][1] = fmaf(s1, r0[i0 + 1], sev[0][1]);
        sev[0][2] = fmaf(s2, r0[i0 + 2], sev[0][2]);
        sev[1][0] = fmaf(s0, r1[i0],     sev[1][0]);
        sev[1][1] = fmaf(s1, r1[i0 + 1], sev[1][1]);
        sev[1][2] = fmaf(s2, r1[i0 + 2], sev[1][2]);
    }

    // Phase D: scale, write out_pre, accumulate out-BN stats
    float fsv = fsv_p[0], fsve = fsve_p[0];
    #pragma unroll
    for (int cl = 0; cl < 2; cl++) {
        int c = c0 + cl;
        float a0 = svv[cl][0] * fsv,  a1 = svv[cl][1] * fsv,  a2 = svv[cl][2] * fsv;
        float e0 = sev[cl][0] * fsve, e1 = sev[cl][1] * fsve, e2 = sev[cl][2] * fsve;
        int o_sv = g * 32 + c * 2;                    // s=0 row; s=1 row is +1
        float* p = d_outpre + b * 12288 + o_sv * 48 + i0;
        p[0]  = a0; p[1]  = a1; p[2]  = a2;
        p[48] = e0; p[49] = e1; p[50] = e2;
        atomicAdd(&sst[(c * 2) * 2],     a0 + a1 + a2);
        atomicAdd(&sst[(c * 2) * 2 + 1], a0 * a0 + a1 * a1 + a2 * a2);
        atomicAdd(&sst[(c * 2 + 1) * 2],     e0 + e1 + e2);
        atomicAdd(&sst[(c * 2 + 1) * 2 + 1], e0 * e0 + e1 * e1 + e2 * e2);
    }
    __syncthreads();
    if (tid < 32) {
        atomicAdd(&d_osum[g * 32 + tid], sst[tid * 2]);
        atomicAdd(&d_osq[g * 32 + tid],  sst[tid * 2 + 1]);
    }
}

__global__ void k_fin_out(const float* __restrict__ gout, const float* __restrict__ bout) {
    int o = threadIdx.x;
    float n = 110592.0f;
    float m = d_osum[o] / n;
    float var = d_osq[o] / n - m * m;
    float sc = rsqrtf(var + EPSV) * gout[o];
    d_oscale[o] = sc;
    d_oshift[o] = bout[o] - m * sc;
}

// ------- pass 4: out BN + s-pair sum + transpose to (gc, h, w, d) ----------
__global__ void k_out(float* __restrict__ out) {
    __shared__ float tile[48 * 49];
    int tid = threadIdx.x;
    int w = blockIdx.x % 48, gc = blockIdx.x / 48;
    int o0 = gc * 2, o1 = o0 + 1;
    float s0 = d_oscale[o0], s1 = d_oscale[o1];
    float sh = d_oshift[o0] + d_oshift[o1];
    #pragma unroll
    for (int t = 0; t < 9; t++) {
        int idx = t * 256 + tid;           // 2304 elements
        int d = idx / 48, h = idx % 48;
        int bb = w * 48 + d;
        float v = d_outpre[bb * 12288 + o0 * 48 + h] * s0
                + d_outpre[bb * 12288 + o1 * 48 + h] * s1 + sh;
        tile[h * 49 + d] = v;
    }
    __syncthreads();
    #pragma unroll
    for (int t = 0; t < 9; t++) {
        int idx = t * 256 + tid;
        int h = idx / 48, d = idx % 48;
        out[gc * NHWD + h * 2304 + w * 48 + d] = tile[h * 49 + d];
    }
}

// ---------------------------------------------------------------------------
extern "C" void kernel_launch(void* const* d_in, const int* in_sizes, int n_in,
                              void* d_out, int out_size) {
    const float* x    = (const float*)d_in[0];
    const float* Wkv  = (const float*)d_in[1];
    const float* Wq   = (const float*)d_in[2];
    const float* gkv  = (const float*)d_in[3];
    const float* bkv  = (const float*)d_in[4];
    const float* gq   = (const float*)d_in[5];
    const float* bq   = (const float*)d_in[6];
    const float* gsim = (const float*)d_in[7];
    const float* bsim = (const float*)d_in[8];
    const float* gout = (const float*)d_in[9];
    const float* bout = (const float*)d_in[10];
    const float* rel  = (const float*)d_in[11];
    const float* fqr  = (const float*)d_in[12];
    const float* fkr  = (const float*)d_in[13];
    const float* fsv  = (const float*)d_in[14];
    const float* fsve = (const float*)d_in[15];
    float* out = (float*)d_out;

    const int proj_smem = (256 * 65 + 64 * 64) * (int)sizeof(float);  // ~83 KB
    cudaFuncSetAttribute(k_proj, cudaFuncAttributeMaxDynamicSharedMemorySize, proj_smem);

    k_init<<<1, 256>>>();
    k_proj<<<1728, 256, proj_smem>>>(x, Wkv, Wq);
    k_fin_proj<<<1, 256>>>(gkv, bkv, gq, bq);
    k_simstat<<<18432, 128>>>(rel, fqr, fkr);
    k_fin_sim<<<1, 32>>>(gsim, bsim);
    k_attn<<<18432, 128>>>(rel, fqr, fkr, fsv, fsve);
    k_fin_out<<<1, 256>>>(gout, bout);
    k_out<<<6144, 256>>>(out);
}

// round 4
// speedup vs baseline: 1.0014x; 1.0014x over previous
#include <cuda_runtime.h>
#include <math.h>

// Problem constants
#define H48   48
#define NG    8
#define NC    64
#define NB    2304        // W*D = 48*48
#define NHWD  110592      // H*W*D
#define NOC   256         // 192 kv channels + 64 q channels
#define RELW  95          // 2*K-1
#define EPSV  1e-5f

// ---------------- scratch (device globals; no allocations) ----------------
__device__ float d_proj[NOC * NHWD];        // [o][b*48 + h]   113 MB
__device__ float d_outpre[NB * NOC * H48];  // [b][o*48 + h]   113 MB
__device__ float d_psum[NOC], d_psq[NOC], d_pscale[NOC], d_pshift[NOC];
__device__ float d_ssum[24],  d_ssq[24],  d_sscale[24],  d_sshift[24];
__device__ float d_osum[NOC], d_osq[NOC], d_oscale[NOC], d_oshift[NOC];

// ---------------- init: zero stat accumulators each launch ----------------
__global__ void k_init() {
    int t = threadIdx.x;
    if (t < NOC) { d_psum[t] = 0.f; d_psq[t] = 0.f; d_osum[t] = 0.f; d_osq[t] = 0.f; }
    if (t < 24)  { d_ssum[t] = 0.f; d_ssq[t]  = 0.f; }
}

// ---------------- pass 1: projection GEMM + per-channel stats --------------
// out[o][b][h] = sum_c W[o][c] * x[c][h][b],  b = w*48+d
// Block: all 256 channels x (8 b x 8 h) spatial tile. 256 threads.
// Thread (og, bl): 8 channels (og*8+i) x 8 h values at fixed b. float4 stores.
__global__ void k_proj(const float* __restrict__ x,
                       const float* __restrict__ Wkv,
                       const float* __restrict__ Wq) {
    extern __shared__ float sm[];
    float* Ws = sm;              // 256 x 65 (padded)
    float* Xs = sm + 256 * 65;   // 64 x 64 : [c][hl*8+bl]
    int tid = threadIdx.x;
    int bt = blockIdx.x % 288, ht = blockIdx.x / 288;
    int b0 = bt * 8, h0 = ht * 8;

    for (int idx = tid; idx < 256 * 64; idx += 256) {
        int o = idx >> 6, c = idx & 63;
        Ws[o * 65 + c] = (o < 192) ? Wkv[o * 64 + c] : Wq[(o - 192) * 64 + c];
    }
    #pragma unroll
    for (int t = 0; t < 16; t++) {
        int idx = t * 256 + tid;
        int c = idx >> 6, sp = idx & 63;
        int hl = sp >> 3, bl = sp & 7;
        Xs[c * 64 + sp] = x[c * NHWD + (h0 + hl) * 2304 + b0 + bl];
    }
    __syncthreads();

    int og = tid >> 3, bl = tid & 7;
    float acc[8][8];
    #pragma unroll
    for (int i = 0; i < 8; i++)
        #pragma unroll
        for (int h = 0; h < 8; h++) acc[i][h] = 0.f;

    #pragma unroll 4
    for (int c = 0; c < 64; c++) {
        float xv[8];
        #pragma unroll
        for (int hl = 0; hl < 8; hl++) xv[hl] = Xs[c * 64 + hl * 8 + bl];
        #pragma unroll
        for (int i = 0; i < 8; i++) {
            float wv = Ws[(og * 8 + i) * 65 + c];
            #pragma unroll
            for (int hl = 0; hl < 8; hl++) acc[i][hl] = fmaf(wv, xv[hl], acc[i][hl]);
        }
    }

    #pragma unroll
    for (int i = 0; i < 8; i++) {
        int o = og * 8 + i;
        float s = 0.f, q = 0.f;
        #pragma unroll
        for (int hl = 0; hl < 8; hl++) { float v = acc[i][hl]; s += v; q += v * v; }
        float* base = d_proj + o * NHWD + (b0 + bl) * 48 + h0;
        *(float4*)(base)     = make_float4(acc[i][0], acc[i][1], acc[i][2], acc[i][3]);
        *(float4*)(base + 4) = make_float4(acc[i][4], acc[i][5], acc[i][6], acc[i][7]);
        s += __shfl_down_sync(0xffffffffu, s, 4, 8);
        s += __shfl_down_sync(0xffffffffu, s, 2, 8);
        s += __shfl_down_sync(0xffffffffu, s, 1, 8);
        q += __shfl_down_sync(0xffffffffu, q, 4, 8);
        q += __shfl_down_sync(0xffffffffu, q, 2, 8);
        q += __shfl_down_sync(0xffffffffu, q, 1, 8);
        if (bl == 0) { atomicAdd(&d_psum[o], s); atomicAdd(&d_psq[o], q); }
    }
}

__global__ void k_fin_proj(const float* __restrict__ gkv, const float* __restrict__ bkv,
                           const float* __restrict__ gq,  const float* __restrict__ bq) {
    int o = threadIdx.x;
    float n = 110592.0f;
    float m = d_psum[o] / n;
    float var = d_psq[o] / n - m * m;
    float g = (o < 192) ? gkv[o] : gq[o - 192];
    float bb = (o < 192) ? bkv[o] : bq[o - 192];
    float sc = rsqrtf(var + EPSV) * g;
    d_pscale[o] = sc;
    d_pshift[o] = bb - m * sc;
}

// ------------- shared logit micro-kernel: 3i x 6j tile, c-loop unrolled ----
__device__ __forceinline__ void compute_logits(const float (*qs)[48], const float (*ks)[48],
                                               const float (*rl)[96], int i0, int j0,
                                               float* A, float* Bq, float* Ck) {
    #pragma unroll
    for (int e = 0; e < 18; e++) { A[e] = 0.f; Bq[e] = 0.f; Ck[e] = 0.f; }
    #pragma unroll
    for (int c = 0; c < 8; c++) {
        float qv[3], kv[6], rq[8], rk[8];
        #pragma unroll
        for (int di = 0; di < 3; di++) qv[di] = qs[c][i0 + di];
        #pragma unroll
        for (int dj = 0; dj < 6; dj++) kv[dj] = ks[c][j0 + dj];
        const float* rqp = &rl[c][0]     + (i0 - j0 + 42);  // d = i-j+47
        const float* rkp = &rl[8 + c][0] + (j0 - i0 + 45);  // d = j-i+47
        #pragma unroll
        for (int t = 0; t < 8; t++) { rq[t] = rqp[t]; rk[t] = rkp[t]; }
        #pragma unroll
        for (int di = 0; di < 3; di++)
            #pragma unroll
            for (int dj = 0; dj < 6; dj++) {
                int e = di * 6 + dj;
                A[e]  = fmaf(qv[di], kv[dj],           A[e]);
                Bq[e] = fmaf(qv[di], rq[di + 5 - dj],  Bq[e]);
                Ck[e] = fmaf(kv[dj], rk[dj + 2 - di],  Ck[e]);
            }
    }
}

// ---------------- pass 2: sim BN stats (qk/qr/kr, 24 channels) -------------
__global__ void k_simstat(const float* __restrict__ rel,
                          const float* __restrict__ fqr_p, const float* __restrict__ fkr_p) {
    __shared__ float qs[8][48], ks[8][48], rl[16][96];
    __shared__ float red[24];
    int tid = threadIdx.x;
    int b = blockIdx.x >> 3, g = blockIdx.x & 7;

    for (int idx = tid; idx < 384; idx += 128) {
        int c = idx / 48, h = idx % 48;
        int oq = 192 + g * 8 + c;
        qs[c][h] = d_proj[oq * NHWD + b * 48 + h] * d_pscale[oq] + d_pshift[oq];
        int ok = g * 24 + c;
        ks[c][h] = d_proj[ok * NHWD + b * 48 + h] * d_pscale[ok] + d_pshift[ok];
    }
    for (int idx = tid; idx < 16 * 95; idx += 128)
        rl[idx / 95][idx % 95] = rel[idx];
    __syncthreads();

    float fqr = fqr_p[0], fkr = fkr_p[0];
    int i0 = (tid >> 3) * 3, j0 = (tid & 7) * 6;
    float A[18], Bq[18], Ck[18];
    compute_logits(qs, ks, rl, i0, j0, A, Bq, Ck);

    float st[6] = {0.f, 0.f, 0.f, 0.f, 0.f, 0.f};
    #pragma unroll
    for (int e = 0; e < 18; e++) {
        float a = A[e];        st[0] += a; st[1] += a * a;
        float bb = Bq[e] * fqr; st[2] += bb; st[3] += bb * bb;
        float cc = Ck[e] * fkr; st[4] += cc; st[5] += cc * cc;
    }
    #pragma unroll
    for (int t = 0; t < 6; t++)
        #pragma unroll
        for (int off = 16; off; off >>= 1)
            st[t] += __shfl_xor_sync(0xffffffffu, st[t], off);
    int w = tid >> 5;
    if ((tid & 31) == 0)
        #pragma unroll
        for (int t = 0; t < 6; t++) red[w * 6 + t] = st[t];
    __syncthreads();
    if (tid < 6) {
        float v = red[tid] + red[6 + tid] + red[12 + tid] + red[18 + tid];
        int ch = g + (tid >> 1) * 8;
        if (tid & 1) atomicAdd(&d_ssq[ch], v); else atomicAdd(&d_ssum[ch], v);
    }
}

__global__ void k_fin_sim(const float* __restrict__ gsim, const float* __restrict__ bsim) {
    int t = threadIdx.x;
    if (t < 24) {
        float n = 5308416.0f;   // B*H*H
        float m = d_ssum[t] / n;
        float var = d_ssq[t] / n - m * m;
        float sc = rsqrtf(var + EPSV) * gsim[t];
        d_sscale[t] = sc;
        d_sshift[t] = bsim[t] - m * sc;
    }
}

// ------- pass 3: logits (BN'd, summed) + softmax + sv/sve + out stats ------
__global__ void k_attn(const float* __restrict__ rel,
                       const float* __restrict__ fqr_p, const float* __restrict__ fkr_p,
                       const float* __restrict__ fsv_p, const float* __restrict__ fsve_p) {
    __shared__ float qs[8][48], ks[8][48], vs[16][48], rl[32][96];
    __shared__ float S[48 * 48];
    __shared__ float sst[64];
    int tid = threadIdx.x;
    int b = blockIdx.x >> 3, g = blockIdx.x & 7;
    if (tid < 64) sst[tid] = 0.f;

    for (int idx = tid; idx < 384; idx += 128) {
        int c = idx / 48, h = idx % 48;
        int oq = 192 + g * 8 + c;
        qs[c][h] = d_proj[oq * NHWD + b * 48 + h] * d_pscale[oq] + d_pshift[oq];
        int ok = g * 24 + c;
        ks[c][h] = d_proj[ok * NHWD + b * 48 + h] * d_pscale[ok] + d_pshift[ok];
    }
    for (int idx = tid; idx < 768; idx += 128) {
        int c = idx / 48, h = idx % 48;
        int ov = g * 24 + 8 + c;
        vs[c][h] = d_proj[ov * NHWD + b * 48 + h] * d_pscale[ov] + d_pshift[ov];
    }
    for (int idx = tid; idx < 32 * 95; idx += 128)
        rl[idx / 95][idx % 95] = rel[idx];
    __syncthreads();

    float fqr = fqr_p[0], fkr = fkr_p[0];
    float ca  = d_sscale[g];
    float cb  = d_sscale[8 + g]  * fqr;
    float cc2 = d_sscale[16 + g] * fkr;
    float shc = d_sshift[g] + d_sshift[8 + g] + d_sshift[16 + g];

    // Phase A: BN'd summed logits into shared S
    {
        int i0 = (tid >> 3) * 3, j0 = (tid & 7) * 6;
        float A[18], Bq[18], Ck[18];
        compute_logits(qs, ks, rl, i0, j0, A, Bq, Ck);
        #pragma unroll
        for (int di = 0; di < 3; di++)
            #pragma unroll
            for (int dj = 0; dj < 6; dj++) {
                int e = di * 6 + dj;
                S[(i0 + di) * 48 + (j0 + dj)] = fmaf(A[e], ca, fmaf(Bq[e], cb, fmaf(Ck[e], cc2, shc)));
            }
    }
    __syncthreads();

    // Phase B: softmax over j (one warp per row, 4 warps x 12 rows)
    {
        int w = tid >> 5, lane = tid & 31;
        for (int t = 0; t < 12; t++) {
            int r = w * 12 + t;
            float v0 = S[r * 48 + lane];
            float v1 = (lane < 16) ? S[r * 48 + 32 + lane] : -1e30f;
            float m = fmaxf(v0, v1);
            #pragma unroll
            for (int off = 16; off; off >>= 1) m = fmaxf(m, __shfl_xor_sync(0xffffffffu, m, off));
            float e0 = __expf(v0 - m);
            float e1 = (lane < 16) ? __expf(v1 - m) : 0.f;
            float s = e0 + e1;
            #pragma unroll
            for (int off = 16; off; off >>= 1) s += __shfl_xor_sync(0xffffffffu, s, off);
            float inv = 1.f / s;
            S[r * 48 + lane] = e0 * inv;
            if (lane < 16) S[r * 48 + 32 + lane] = e1 * inv;
        }
    }
    __syncthreads();

    // Phase C: sv + sve; thread tile = 2 channels x 3 rows
    int c0 = (tid & 7) * 2, i0 = (tid >> 3) * 3;
    float svv[2][3] = {{0.f,0.f,0.f},{0.f,0.f,0.f}};
    float sev[2][3] = {{0.f,0.f,0.f},{0.f,0.f,0.f}};
    #pragma unroll 4
    for (int j = 0; j < 48; j++) {
        float s0 = S[i0 * 48 + j], s1 = S[(i0 + 1) * 48 + j], s2 = S[(i0 + 2) * 48 + j];
        float v0 = vs[c0][j], v1 = vs[c0 + 1][j];
        svv[0][0] = fmaf(s0, v0, svv[0][0]);
        svv[0][1] = fmaf(s1, v0, svv[0][1]);
        svv[0][2] = fmaf(s2, v0, svv[0][2]);
        svv[1][0] = fmaf(s0, v1, svv[1][0]);
        svv[1][1] = fmaf(s1, v1, svv[1][1]);
        svv[1][2] = fmaf(s2, v1, svv[1][2]);
        const float* r0 = &rl[16 + c0][0] + (47 - j);
        const float* r1 = &rl[17 + c0][0] + (47 - j);
        sev[0][0] = fmaf(s0, r0[i0],     sev[0][0]);
        sev[0][1] = fmaf(s1, r0[i0 + 1], sev[0][1]);
        sev[0][2] = fmaf(s2, r0[i0 + 2], sev[0][2]);
        sev[1][0] = fmaf(s0, r1[i0],     sev[1][0]);
        sev[1][1] = fmaf(s1, r1[i0 + 1], sev[1][1]);
        sev[1][2] = fmaf(s2, r1[i0 + 2], sev[1][2]);
    }

    // Phase D: scale, write out_pre, accumulate out-BN stats
    float fsv = fsv_p[0], fsve = fsve_p[0];
    #pragma unroll
    for (int cl = 0; cl < 2; cl++) {
        int c = c0 + cl;
        float a0 = svv[cl][0] * fsv,  a1 = svv[cl][1] * fsv,  a2 = svv[cl][2] * fsv;
        float e0 = sev[cl][0] * fsve, e1 = sev[cl][1] * fsve, e2 = sev[cl][2] * fsve;
        int o_sv = g * 32 + c * 2;                    // s=0 row; s=1 row is +1
        float* p = d_outpre + b * 12288 + o_sv * 48 + i0;
        p[0]  = a0; p[1]  = a1; p[2]  = a2;
        p[48] = e0; p[49] = e1; p[50] = e2;
        atomicAdd(&sst[(c * 2) * 2],     a0 + a1 + a2);
        atomicAdd(&sst[(c * 2) * 2 + 1], a0 * a0 + a1 * a1 + a2 * a2);
        atomicAdd(&sst[(c * 2 + 1) * 2],     e0 + e1 + e2);
        atomicAdd(&sst[(c * 2 + 1) * 2 + 1], e0 * e0 + e1 * e1 + e2 * e2);
    }
    __syncthreads();
    if (tid < 32) {
        atomicAdd(&d_osum[g * 32 + tid], sst[tid * 2]);
        atomicAdd(&d_osq[g * 32 + tid],  sst[tid * 2 + 1]);
    }
}

__global__ void k_fin_out(const float* __restrict__ gout, const float* __restrict__ bout) {
    int o = threadIdx.x;
    float n = 110592.0f;
    float m = d_osum[o] / n;
    float var = d_osq[o] / n - m * m;
    float sc = rsqrtf(var + EPSV) * gout[o];
    d_oscale[o] = sc;
    d_oshift[o] = bout[o] - m * sc;
}

// ------- pass 4: out BN + s-pair sum + transpose to (gc, h, w, d) ----------
__global__ void k_out(float* __restrict__ out) {
    __shared__ float tile[48 * 49];
    int tid = threadIdx.x;
    int w = blockIdx.x % 48, gc = blockIdx.x / 48;
    int o0 = gc * 2, o1 = o0 + 1;
    float s0 = d_oscale[o0], s1 = d_oscale[o1];
    float sh = d_oshift[o0] + d_oshift[o1];
    #pragma unroll
    for (int t = 0; t < 9; t++) {
        int idx = t * 256 + tid;           // 2304 elements
        int d = idx / 48, h = idx % 48;
        int bb = w * 48 + d;
        float v = d_outpre[bb * 12288 + o0 * 48 + h] * s0
                + d_outpre[bb * 12288 + o1 * 48 + h] * s1 + sh;
        tile[h * 49 + d] = v;
    }
    __syncthreads();
    #pragma unroll
    for (int t = 0; t < 9; t++) {
        int idx = t * 256 + tid;
        int h = idx / 48, d = idx % 48;
        out[gc * NHWD + h * 2304 + w * 48 + d] = tile[h * 49 + d];
    }
}

// ---------------------------------------------------------------------------
extern "C" void kernel_launch(void* const* d_in, const int* in_sizes, int n_in,
                              void* d_out, int out_size) {
    const float* x    = (const float*)d_in[0];
    const float* Wkv  = (const float*)d_in[1];
    const float* Wq   = (const float*)d_in[2];
    const float* gkv  = (const float*)d_in[3];
    const float* bkv  = (const float*)d_in[4];
    const float* gq   = (const float*)d_in[5];
    const float* bq   = (const float*)d_in[6];
    const float* gsim = (const float*)d_in[7];
    const float* bsim = (const float*)d_in[8];
    const float* gout = (const float*)d_in[9];
    const float* bout = (const float*)d_in[10];
    const float* rel  = (const float*)d_in[11];
    const float* fqr  = (const float*)d_in[12];
    const float* fkr  = (const float*)d_in[13];
    const float* fsv  = (const float*)d_in[14];
    const float* fsve = (const float*)d_in[15];
    float* out = (float*)d_out;

    const int proj_smem = (256 * 65 + 64 * 64) * (int)sizeof(float);  // ~83 KB
    cudaFuncSetAttribute(k_proj, cudaFuncAttributeMaxDynamicSharedMemorySize, proj_smem);

    k_init<<<1, 256>>>();
    k_proj<<<1728, 256, proj_smem>>>(x, Wkv, Wq);
    k_fin_proj<<<1, 256>>>(gkv, bkv, gq, bq);
    k_simstat<<<18432, 128>>>(rel, fqr, fkr);
    k_fin_sim<<<1, 32>>>(gsim, bsim);
    k_attn<<<18432, 128>>>(rel, fqr, fkr, fsv, fsve);
    k_fin_out<<<1, 256>>>(gout, bout);
    k_out<<<6144, 256>>>(out);
}

// round 5
// speedup vs baseline: 1.0973x; 1.0958x over previous
#include <cuda_runtime.h>
#include <math.h>

// Problem constants
#define H48   48
#define NG    8
#define NC    64
#define NB    2304        // W*D = 48*48
#define NHWD  110592      // H*W*D
#define NOC   256         // 192 kv channels + 64 q channels
#define EPSV  1e-5f

// ---------------- scratch (device globals; no allocations) ----------------
__device__ float d_proj[NOC * NHWD];        // [o][b*48 + h]   113 MB
__device__ float d_outpre[NB * NOC * H48];  // [b][o*48 + h]   113 MB
__device__ float d_psum[NOC], d_psq[NOC], d_pscale[NOC], d_pshift[NOC];
__device__ float d_ssum[24],  d_ssq[24],  d_sscale[24],  d_sshift[24];
__device__ float d_osum[NOC], d_osq[NOC], d_oscale[NOC], d_oshift[NOC];
// precomputed window tables from rel (batch-independent)
__device__ float d_W1q[8 * 48], d_W1k[8 * 48];
__device__ float d_W2q[36 * 48], d_W2k[36 * 48];   // rows 0-7 diag, 8-35 off-diag(x2)

__device__ __forceinline__ void decode_pair(int op, int& a, int& b) {
    a = 0; int r = op;
    while (r >= 7 - a) { r -= 7 - a; a++; }
    b = a + 1 + r;
}

// ---------------- init: zero stat accumulators each launch ----------------
__global__ void k_init() {
    int t = threadIdx.x;
    if (t < NOC) { d_psum[t] = 0.f; d_psq[t] = 0.f; d_osum[t] = 0.f; d_osq[t] = 0.f; }
    if (t < 24)  { d_ssum[t] = 0.f; d_ssq[t]  = 0.f; }
}

// ---------------- precompute rel window tables -----------------------------
// W1q[c][t] = sum_{d=t..t+47} rel[c][d];  W1k from rows 8..15
// W2q[p][t]: p<8 diag (c,c) undoubled; p>=8 off-diag pair op=p-8 (a<b), x2 baked
__global__ void k_prewin(const float* __restrict__ rel) {
    int tid = threadIdx.x;
    for (int idx = tid; idx < 16 * 48; idx += 256) {
        int r = idx / 48, t = idx % 48;
        float s = 0.f;
        for (int d = 0; d < 48; d++) s += rel[r * 95 + t + d];
        if (r < 8) d_W1q[r * 48 + t] = s; else d_W1k[(r - 8) * 48 + t] = s;
    }
    for (int idx = tid; idx < 72 * 48; idx += 256) {
        int u = idx / 48, t = idx % 48;
        int side = u / 36, p = u % 36;
        int a, b; float f;
        if (p < 8) { a = p; b = p; f = 1.f; } else { decode_pair(p - 8, a, b); f = 2.f; }
        const float* ra = rel + (side * 8 + a) * 95;
        const float* rb = rel + (side * 8 + b) * 95;
        float s = 0.f;
        for (int d = 0; d < 48; d++) s = fmaf(ra[t + d], rb[t + d], s);
        s *= f;
        if (side == 0) d_W2q[p * 48 + t] = s; else d_W2k[p * 48 + t] = s;
    }
}

// ---------------- pass 1: projection GEMM + per-channel stats --------------
__global__ void k_proj(const float* __restrict__ x,
                       const float* __restrict__ Wkv,
                       const float* __restrict__ Wq) {
    extern __shared__ float sm[];
    float* Ws = sm;              // 256 x 65 (padded)
    float* Xs = sm + 256 * 65;   // 64 x 64 : [c][hl*8+bl]
    int tid = threadIdx.x;
    int bt = blockIdx.x % 288, ht = blockIdx.x / 288;
    int b0 = bt * 8, h0 = ht * 8;

    for (int idx = tid; idx < 256 * 64; idx += 256) {
        int o = idx >> 6, c = idx & 63;
        Ws[o * 65 + c] = (o < 192) ? Wkv[o * 64 + c] : Wq[(o - 192) * 64 + c];
    }
    #pragma unroll
    for (int t = 0; t < 16; t++) {
        int idx = t * 256 + tid;
        int c = idx >> 6, sp = idx & 63;
        int hl = sp >> 3, bl = sp & 7;
        Xs[c * 64 + sp] = x[c * NHWD + (h0 + hl) * 2304 + b0 + bl];
    }
    __syncthreads();

    int og = tid >> 3, bl = tid & 7;
    float acc[8][8];
    #pragma unroll
    for (int i = 0; i < 8; i++)
        #pragma unroll
        for (int h = 0; h < 8; h++) acc[i][h] = 0.f;

    #pragma unroll 4
    for (int c = 0; c < 64; c++) {
        float xv[8];
        #pragma unroll
        for (int hl = 0; hl < 8; hl++) xv[hl] = Xs[c * 64 + hl * 8 + bl];
        #pragma unroll
        for (int i = 0; i < 8; i++) {
            float wv = Ws[(og * 8 + i) * 65 + c];
            #pragma unroll
            for (int hl = 0; hl < 8; hl++) acc[i][hl] = fmaf(wv, xv[hl], acc[i][hl]);
        }
    }

    #pragma unroll
    for (int i = 0; i < 8; i++) {
        int o = og * 8 + i;
        float s = 0.f, q = 0.f;
        #pragma unroll
        for (int hl = 0; hl < 8; hl++) { float v = acc[i][hl]; s += v; q += v * v; }
        float* base = d_proj + o * NHWD + (b0 + bl) * 48 + h0;
        *(float4*)(base)     = make_float4(acc[i][0], acc[i][1], acc[i][2], acc[i][3]);
        *(float4*)(base + 4) = make_float4(acc[i][4], acc[i][5], acc[i][6], acc[i][7]);
        s += __shfl_down_sync(0xffffffffu, s, 4, 8);
        s += __shfl_down_sync(0xffffffffu, s, 2, 8);
        s += __shfl_down_sync(0xffffffffu, s, 1, 8);
        q += __shfl_down_sync(0xffffffffu, q, 4, 8);
        q += __shfl_down_sync(0xffffffffu, q, 2, 8);
        q += __shfl_down_sync(0xffffffffu, q, 1, 8);
        if (bl == 0) { atomicAdd(&d_psum[o], s); atomicAdd(&d_psq[o], q); }
    }
}

__global__ void k_fin_proj(const float* __restrict__ gkv, const float* __restrict__ bkv,
                           const float* __restrict__ gq,  const float* __restrict__ bq) {
    int o = threadIdx.x;
    float n = 110592.0f;
    float m = d_psum[o] / n;
    float var = d_psq[o] / n - m * m;
    float g = (o < 192) ? gkv[o] : gq[o - 192];
    float bb = (o < 192) ? bkv[o] : bq[o - 192];
    float sc = rsqrtf(var + EPSV) * g;
    d_pscale[o] = sc;
    d_pshift[o] = bb - m * sc;
}

// ------------- pass 2: sim BN stats via Gram factorization -----------------
// block = b (2304 blocks), 256 threads = 8 warps, warp w = group g.
__global__ __launch_bounds__(256) void k_simstat2(const float* __restrict__ fqr_p,
                                                  const float* __restrict__ fkr_p) {
    __shared__ float qs[64 * 49], ks[64 * 49];
    __shared__ float sW2q[36 * 49], sW2k[36 * 49];
    __shared__ float sW1q[8 * 48], sW1k[8 * 48];
    int tid = threadIdx.x;
    int b = blockIdx.x;
    int g = tid >> 5, lane = tid & 31;

    for (int idx = tid; idx < 64 * 48; idx += 256) {
        int c64 = idx / 48, h = idx % 48;
        int oq = 192 + c64;
        qs[c64 * 49 + h] = d_proj[oq * NHWD + b * 48 + h] * d_pscale[oq] + d_pshift[oq];
        int ok = (c64 >> 3) * 24 + (c64 & 7);
        ks[c64 * 49 + h] = d_proj[ok * NHWD + b * 48 + h] * d_pscale[ok] + d_pshift[ok];
    }
    for (int idx = tid; idx < 36 * 48; idx += 256) {
        int p = idx / 48, t = idx % 48;
        sW2q[p * 49 + t] = d_W2q[idx];
        sW2k[p * 49 + t] = d_W2k[idx];
    }
    for (int idx = tid; idx < 8 * 48; idx += 256) { sW1q[idx] = d_W1q[idx]; sW1k[idx] = d_W1k[idx]; }
    __syncthreads();

    float vsumqk = 0.f, vsqqk = 0.f, vtq = 0.f, vtk = 0.f, vsumqr = 0.f, vsumkr = 0.f;

    if (lane < 28) {  // off-diagonal Gram pairs
        int a, bb2; decode_pair(lane, a, bb2);
        const float* qa = &qs[(g * 8 + a) * 49];
        const float* qb = &qs[(g * 8 + bb2) * 49];
        const float* ka = &ks[(g * 8 + a) * 49];
        const float* kb = &ks[(g * 8 + bb2) * 49];
        const float* w2q = &sW2q[(8 + lane) * 49];
        const float* w2k = &sW2k[(8 + lane) * 49];
        float Qp = 0.f, Kp = 0.f, tq = 0.f, tk = 0.f;
        #pragma unroll 8
        for (int i = 0; i < 48; i++) {
            float qq = qa[i] * qb[i]; Qp += qq; tq = fmaf(qq, w2q[i], tq);
            float kk = ka[i] * kb[i]; Kp += kk; tk = fmaf(kk, w2k[i], tk);
        }
        vsqqk = 2.f * Qp * Kp;   // off-diag counted twice in Gram contraction
        vtq = tq; vtk = tk;      // x2 baked in W2 off-diag rows
    }
    if (lane < 8) {   // per-channel sums + diagonal Gram
        const float* qc = &qs[(g * 8 + lane) * 49];
        const float* kc = &ks[(g * 8 + lane) * 49];
        const float* w2q = &sW2q[lane * 49];
        const float* w2k = &sW2k[lane * 49];
        const float* w1q = &sW1q[lane * 48];
        const float* w1k = &sW1k[lane * 48];
        float Sq = 0.f, Sk = 0.f, Qd = 0.f, Kd = 0.f, tqd = 0.f, tkd = 0.f, sqr = 0.f, skr = 0.f;
        #pragma unroll 8
        for (int i = 0; i < 48; i++) {
            float qv = qc[i], kv = kc[i];
            Sq += qv; Sk += kv;
            float q2 = qv * qv, k2 = kv * kv;
            Qd += q2; Kd += k2;
            tqd = fmaf(q2, w2q[i], tqd);
            tkd = fmaf(k2, w2k[i], tkd);
            sqr = fmaf(qv, w1q[i], sqr);
            skr = fmaf(kv, w1k[i], skr);
        }
        vsumqk = Sq * Sk;
        vsqqk += Qd * Kd;
        vtq += tqd; vtk += tkd;
        vsumqr = sqr; vsumkr = skr;
    }
    #pragma unroll
    for (int off = 16; off; off >>= 1) {
        vsumqk += __shfl_xor_sync(0xffffffffu, vsumqk, off);
        vsqqk  += __shfl_xor_sync(0xffffffffu, vsqqk,  off);
        vtq    += __shfl_xor_sync(0xffffffffu, vtq,    off);
        vtk    += __shfl_xor_sync(0xffffffffu, vtk,    off);
        vsumqr += __shfl_xor_sync(0xffffffffu, vsumqr, off);
        vsumkr += __shfl_xor_sync(0xffffffffu, vsumkr, off);
    }
    if (lane == 0) {
        float fqr = fqr_p[0], fkr = fkr_p[0];
        atomicAdd(&d_ssum[g], vsumqk);
        atomicAdd(&d_ssq[g],  vsqqk);
        atomicAdd(&d_ssum[8 + g], fqr * vsumqr);
        atomicAdd(&d_ssq[8 + g],  fqr * fqr * vtq);
        atomicAdd(&d_ssum[16 + g], fkr * vsumkr);
        atomicAdd(&d_ssq[16 + g],  fkr * fkr * vtk);
    }
}

__global__ void k_fin_sim(const float* __restrict__ gsim, const float* __restrict__ bsim) {
    int t = threadIdx.x;
    if (t < 24) {
        float n = 5308416.0f;   // B*H*H
        float m = d_ssum[t] / n;
        float var = d_ssq[t] / n - m * m;
        float sc = rsqrtf(var + EPSV) * gsim[t];
        d_sscale[t] = sc;
        d_sshift[t] = bsim[t] - m * sc;
    }
}

// ------- pass 3: logits (pre-folded BN scales) + softmax + sv/sve ----------
__global__ __launch_bounds__(128) void k_attn(const float* __restrict__ rel,
                       const float* __restrict__ fqr_p, const float* __restrict__ fkr_p,
                       const float* __restrict__ fsv_p, const float* __restrict__ fsve_p) {
    __shared__ float sqA[8][48], sqR[8][48], skR[8][48], svs[16][48];
    __shared__ float srq[8][96], srk[8][96], sve[16][96];
    __shared__ float S[48 * 48];
    __shared__ float sst[64];
    int tid = threadIdx.x;
    int b = blockIdx.x >> 3, g = blockIdx.x & 7;
    if (tid < 64) sst[tid] = 0.f;

    float fqr = fqr_p[0], fkr = fkr_p[0], fsv = fsv_p[0], fsve = fsve_p[0];
    float ca  = d_sscale[g];
    float cb  = d_sscale[8 + g]  * fqr;
    float cc2 = d_sscale[16 + g] * fkr;

    for (int idx = tid; idx < 384; idx += 128) {
        int c = idx / 48, h = idx % 48;
        int oq = 192 + g * 8 + c;
        float qv = d_proj[oq * NHWD + b * 48 + h] * d_pscale[oq] + d_pshift[oq];
        sqR[c][h] = qv;
        sqA[c][h] = ca * qv;
        int ok = g * 24 + c;
        skR[c][h] = d_proj[ok * NHWD + b * 48 + h] * d_pscale[ok] + d_pshift[ok];
    }
    for (int idx = tid; idx < 768; idx += 128) {
        int c = idx / 48, h = idx % 48;
        int ov = g * 24 + 8 + c;
        svs[c][h] = fsv * (d_proj[ov * NHWD + b * 48 + h] * d_pscale[ov] + d_pshift[ov]);
    }
    for (int idx = tid; idx < 32 * 95; idx += 128) {
        int r = idx / 95, d = idx % 95;
        float v = rel[idx];
        if (r < 8)       srq[r][d]      = cb  * v;
        else if (r < 16) srk[r - 8][d]  = cc2 * v;
        else             sve[r - 16][d] = fsve * v;
    }
    __syncthreads();

    // Phase A: fused logits (BN shift dropped — softmax invariant)
    {
        int i0 = (tid >> 3) * 3, j0 = (tid & 7) * 6;
        float L[18];
        #pragma unroll
        for (int e = 0; e < 18; e++) L[e] = 0.f;
        #pragma unroll
        for (int c = 0; c < 8; c++) {
            float qa[3], qr[3], kv[6], rqv[8], rkv[8];
            #pragma unroll
            for (int di = 0; di < 3; di++) { qa[di] = sqA[c][i0 + di]; qr[di] = sqR[c][i0 + di]; }
            #pragma unroll
            for (int dj = 0; dj < 6; dj++) kv[dj] = skR[c][j0 + dj];
            const float* rqp = &srq[c][0] + (i0 - j0 + 42);  // d = i-j+47
            const float* rkp = &srk[c][0] + (j0 - i0 + 45);  // d = j-i+47
            #pragma unroll
            for (int t = 0; t < 8; t++) { rqv[t] = rqp[t]; rkv[t] = rkp[t]; }
            #pragma unroll
            for (int di = 0; di < 3; di++)
                #pragma unroll
                for (int dj = 0; dj < 6; dj++) {
                    int e = di * 6 + dj;
                    L[e] = fmaf(kv[dj], qa[di],            L[e]);
                    L[e] = fmaf(kv[dj], rkv[dj + 2 - di],  L[e]);
                    L[e] = fmaf(qr[di], rqv[di + 5 - dj],  L[e]);
                }
        }
        #pragma unroll
        for (int di = 0; di < 3; di++)
            #pragma unroll
            for (int dj = 0; dj < 6; dj++)
                S[(i0 + di) * 48 + (j0 + dj)] = L[di * 6 + dj];
    }
    __syncthreads();

    // Phase B: softmax over j (one warp per 12 rows)
    {
        int w = tid >> 5, lane = tid & 31;
        for (int t = 0; t < 12; t++) {
            int r = w * 12 + t;
            float v0 = S[r * 48 + lane];
            float v1 = (lane < 16) ? S[r * 48 + 32 + lane] : -1e30f;
            float m = fmaxf(v0, v1);
            #pragma unroll
            for (int off = 16; off; off >>= 1) m = fmaxf(m, __shfl_xor_sync(0xffffffffu, m, off));
            float e0 = __expf(v0 - m);
            float e1 = (lane < 16) ? __expf(v1 - m) : 0.f;
            float s = e0 + e1;
            #pragma unroll
            for (int off = 16; off; off >>= 1) s += __shfl_xor_sync(0xffffffffu, s, off);
            float inv = 1.f / s;
            S[r * 48 + lane] = e0 * inv;
            if (lane < 16) S[r * 48 + 32 + lane] = e1 * inv;
        }
    }
    __syncthreads();

    // Phase C: sv + sve (v and ve pre-scaled by fsv/fsve)
    int c0 = (tid & 7) * 2, i0 = (tid >> 3) * 3;
    float svv[2][3] = {{0.f,0.f,0.f},{0.f,0.f,0.f}};
    float sev[2][3] = {{0.f,0.f,0.f},{0.f,0.f,0.f}};
    #pragma unroll 4
    for (int j = 0; j < 48; j++) {
        float s0 = S[i0 * 48 + j], s1 = S[(i0 + 1) * 48 + j], s2 = S[(i0 + 2) * 48 + j];
        float v0 = svs[c0][j], v1 = svs[c0 + 1][j];
        svv[0][0] = fmaf(s0, v0, svv[0][0]);
        svv[0][1] = fmaf(s1, v0, svv[0][1]);
        svv[0][2] = fmaf(s2, v0, svv[0][2]);
        svv[1][0] = fmaf(s0, v1, svv[1][0]);
        svv[1][1] = fmaf(s1, v1, svv[1][1]);
        svv[1][2] = fmaf(s2, v1, svv[1][2]);
        const float* r0 = &sve[c0][0] + (47 - j);
        const float* r1 = &sve[c0 + 1][0] + (47 - j);
        sev[0][0] = fmaf(s0, r0[i0],     sev[0][0]);
        sev[0][1] = fmaf(s1, r0[i0 + 1], sev[0][1]);
        sev[0][2] = fmaf(s2, r0[i0 + 2], sev[0][2]);
        sev[1][0] = fmaf(s0, r1[i0],     sev[1][0]);
        sev[1][1] = fmaf(s1, r1[i0 + 1], sev[1][1]);
        sev[1][2] = fmaf(s2, r1[i0 + 2], sev[1][2]);
    }

    // Phase D: write out_pre, accumulate out-BN stats
    #pragma unroll
    for (int cl = 0; cl < 2; cl++) {
        int c = c0 + cl;
        float a0 = svv[cl][0], a1 = svv[cl][1], a2 = svv[cl][2];
        float e0 = sev[cl][0], e1 = sev[cl][1], e2 = sev[cl][2];
        int o_sv = g * 32 + c * 2;
        float* p = d_outpre + b * 12288 + o_sv * 48 + i0;
        p[0]  = a0; p[1]  = a1; p[2]  = a2;
        p[48] = e0; p[49] = e1; p[50] = e2;
        atomicAdd(&sst[(c * 2) * 2],     a0 + a1 + a2);
        atomicAdd(&sst[(c * 2) * 2 + 1], a0 * a0 + a1 * a1 + a2 * a2);
        atomicAdd(&sst[(c * 2 + 1) * 2],     e0 + e1 + e2);
        atomicAdd(&sst[(c * 2 + 1) * 2 + 1], e0 * e0 + e1 * e1 + e2 * e2);
    }
    __syncthreads();
    if (tid < 32) {
        atomicAdd(&d_osum[g * 32 + tid], sst[tid * 2]);
        atomicAdd(&d_osq[g * 32 + tid],  sst[tid * 2 + 1]);
    }
}

__global__ void k_fin_out(const float* __restrict__ gout, const float* __restrict__ bout) {
    int o = threadIdx.x;
    float n = 110592.0f;
    float m = d_osum[o] / n;
    float var = d_osq[o] / n - m * m;
    float sc = rsqrtf(var + EPSV) * gout[o];
    d_oscale[o] = sc;
    d_oshift[o] = bout[o] - m * sc;
}

// ------- pass 4: out BN + s-pair sum + transpose to (gc, h, w, d) ----------
__global__ void k_out(float* __restrict__ out) {
    __shared__ float tile[48 * 49];
    int tid = threadIdx.x;
    int w = blockIdx.x % 48, gc = blockIdx.x / 48;
    int o0 = gc * 2, o1 = o0 + 1;
    float s0 = d_oscale[o0], s1 = d_oscale[o1];
    float sh = d_oshift[o0] + d_oshift[o1];
    #pragma unroll
    for (int t = 0; t < 9; t++) {
        int idx = t * 256 + tid;
        int d = idx / 48, h = idx % 48;
        int bb = w * 48 + d;
        float v = d_outpre[bb * 12288 + o0 * 48 + h] * s0
                + d_outpre[bb * 12288 + o1 * 48 + h] * s1 + sh;
        tile[h * 49 + d] = v;
    }
    __syncthreads();
    #pragma unroll
    for (int t = 0; t < 9; t++) {
        int idx = t * 256 + tid;
        int h = idx / 48, d = idx % 48;
        out[gc * NHWD + h * 2304 + w * 48 + d] = tile[h * 49 + d];
    }
}

// ---------------------------------------------------------------------------
extern "C" void kernel_launch(void* const* d_in, const int* in_sizes, int n_in,
                              void* d_out, int out_size) {
    const float* x    = (const float*)d_in[0];
    const float* Wkv  = (const float*)d_in[1];
    const float* Wq   = (const float*)d_in[2];
    const float* gkv  = (const float*)d_in[3];
    const float* bkv  = (const float*)d_in[4];
    const float* gq   = (const float*)d_in[5];
    const float* bq   = (const float*)d_in[6];
    const float* gsim = (const float*)d_in[7];
    const float* bsim = (const float*)d_in[8];
    const float* gout = (const float*)d_in[9];
    const float* bout = (const float*)d_in[10];
    const float* rel  = (const float*)d_in[11];
    const float* fqr  = (const float*)d_in[12];
    const float* fkr  = (const float*)d_in[13];
    const float* fsv  = (const float*)d_in[14];
    const float* fsve = (const float*)d_in[15];
    float* out = (float*)d_out;

    const int proj_smem = (256 * 65 + 64 * 64) * (int)sizeof(float);  // ~83 KB
    cudaFuncSetAttribute(k_proj, cudaFuncAttributeMaxDynamicSharedMemorySize, proj_smem);

    k_init<<<1, 256>>>();
    k_prewin<<<1, 256>>>(rel);
    k_proj<<<1728, 256, proj_smem>>>(x, Wkv, Wq);
    k_fin_proj<<<1, 256>>>(gkv, bkv, gq, bq);
    k_simstat2<<<2304, 256>>>(fqr, fkr);
    k_fin_sim<<<1, 32>>>(gsim, bsim);
    k_attn<<<18432, 128>>>(rel, fqr, fkr, fsv, fsve);
    k_fin_out<<<1, 256>>>(gout, bout);
    k_out<<<6144, 256>>>(out);
}

// round 6
// speedup vs baseline: 1.4535x; 1.3247x over previous
#include <cuda_runtime.h>
#include <math.h>

#define H48   48
#define NG    8
#define NC    64
#define NB    2304
#define NHWD  110592
#define NOC   256
#define EPSV  1e-5f

// ---------------- scratch ----------------
__device__ float d_proj[NOC * NHWD];        // [o][b*48 + h]
__device__ float d_outpre[NB * NOC * H48];  // [b][g*1536 + o_local*48 + i]
__device__ float d_psum[NOC], d_psq[NOC];
__device__ float d_ssum[24],  d_ssq[24];
__device__ float d_osum[NOC], d_osq[NOC];
__device__ float d_W1q[8 * 48], d_W1k[8 * 48];
__device__ float d_W2q[36 * 48], d_W2k[36 * 48];

__device__ __forceinline__ void decode_pair(int op, int& a, int& b) {
    a = 0; int r = op;
    while (r >= 7 - a) { r -= 7 - a; a++; }
    b = a + 1 + r;
}

// ------------- pass 0: zero accumulators + rel window tables --------------
__global__ void k_pre(const float* __restrict__ rel) {
    int tid = threadIdx.x;
    if (blockIdx.x == 0) {
        if (tid < NOC) { d_psum[tid] = 0.f; d_psq[tid] = 0.f; d_osum[tid] = 0.f; d_osq[tid] = 0.f; }
        if (tid < 24)  { d_ssum[tid] = 0.f; d_ssq[tid]  = 0.f; }
        for (int idx = tid; idx < 16 * 48; idx += 256) {
            int r = idx / 48, t = idx % 48;
            float s = 0.f;
            for (int d = 0; d < 48; d++) s += rel[r * 95 + t + d];
            if (r < 8) d_W1q[r * 48 + t] = s; else d_W1k[(r - 8) * 48 + t] = s;
        }
    } else {
        for (int idx = tid; idx < 24 * 48; idx += 256) {
            int u = (blockIdx.x - 1) * 24 + idx / 48, t = idx % 48;
            int side = u / 36, p = u % 36;
            int a, b; float f;
            if (p < 8) { a = p; b = p; f = 1.f; } else { decode_pair(p - 8, a, b); f = 2.f; }
            const float* ra = rel + (side * 8 + a) * 95;
            const float* rb = rel + (side * 8 + b) * 95;
            float s = 0.f;
            for (int d = 0; d < 48; d++) s = fmaf(ra[t + d], rb[t + d], s);
            s *= f;
            if (side == 0) d_W2q[p * 48 + t] = s; else d_W2k[p * 48 + t] = s;
        }
    }
}

// ---------------- pass 1: projection GEMM + per-channel stats --------------
__global__ void k_proj(const float* __restrict__ x,
                       const float* __restrict__ Wkv,
                       const float* __restrict__ Wq) {
    extern __shared__ float sm[];
    float* Ws = sm;              // 256 x 65
    float* Xs = sm + 256 * 65;   // 64 x 64
    int tid = threadIdx.x;
    int bt = blockIdx.x % 288, ht = blockIdx.x / 288;
    int b0 = bt * 8, h0 = ht * 8;

    for (int idx = tid; idx < 256 * 64; idx += 256) {
        int o = idx >> 6, c = idx & 63;
        Ws[o * 65 + c] = (o < 192) ? Wkv[o * 64 + c] : Wq[(o - 192) * 64 + c];
    }
    #pragma unroll
    for (int t = 0; t < 16; t++) {
        int idx = t * 256 + tid;
        int c = idx >> 6, sp = idx & 63;
        int hl = sp >> 3, bl = sp & 7;
        Xs[c * 64 + sp] = x[c * NHWD + (h0 + hl) * 2304 + b0 + bl];
    }
    __syncthreads();

    int og = tid >> 3, bl = tid & 7;
    float acc[8][8];
    #pragma unroll
    for (int i = 0; i < 8; i++)
        #pragma unroll
        for (int h = 0; h < 8; h++) acc[i][h] = 0.f;

    #pragma unroll 4
    for (int c = 0; c < 64; c++) {
        float xv[8];
        #pragma unroll
        for (int hl = 0; hl < 8; hl++) xv[hl] = Xs[c * 64 + hl * 8 + bl];
        #pragma unroll
        for (int i = 0; i < 8; i++) {
            float wv = Ws[(og * 8 + i) * 65 + c];
            #pragma unroll
            for (int hl = 0; hl < 8; hl++) acc[i][hl] = fmaf(wv, xv[hl], acc[i][hl]);
        }
    }

    #pragma unroll
    for (int i = 0; i < 8; i++) {
        int o = og * 8 + i;
        float s = 0.f, q = 0.f;
        #pragma unroll
        for (int hl = 0; hl < 8; hl++) { float v = acc[i][hl]; s += v; q += v * v; }
        float* base = d_proj + o * NHWD + (b0 + bl) * 48 + h0;
        *(float4*)(base)     = make_float4(acc[i][0], acc[i][1], acc[i][2], acc[i][3]);
        *(float4*)(base + 4) = make_float4(acc[i][4], acc[i][5], acc[i][6], acc[i][7]);
        s += __shfl_down_sync(0xffffffffu, s, 4, 8);
        s += __shfl_down_sync(0xffffffffu, s, 2, 8);
        s += __shfl_down_sync(0xffffffffu, s, 1, 8);
        q += __shfl_down_sync(0xffffffffu, q, 4, 8);
        q += __shfl_down_sync(0xffffffffu, q, 2, 8);
        q += __shfl_down_sync(0xffffffffu, q, 1, 8);
        if (bl == 0) { atomicAdd(&d_psum[o], s); atomicAdd(&d_psq[o], q); }
    }
}

// helper: BN scale/shift from raw sums
__device__ __forceinline__ void bn_params(float sum, float sq, float n, float gamma, float beta,
                                          float& sc, float& sh) {
    float m = sum / n;
    float var = sq / n - m * m;
    sc = rsqrtf(var + EPSV) * gamma;
    sh = beta - m * sc;
}

// ------------- pass 2: sim BN stats via Gram factorization -----------------
__global__ __launch_bounds__(256) void k_simstat2(const float* __restrict__ fqr_p,
                                                  const float* __restrict__ fkr_p,
                                                  const float* __restrict__ gkv, const float* __restrict__ bkv,
                                                  const float* __restrict__ gq,  const float* __restrict__ bq) {
    __shared__ float qs[64 * 49], ks[64 * 49];
    __shared__ float sW2q[36 * 49], sW2k[36 * 49];
    __shared__ float sW1q[8 * 48], sW1k[8 * 48];
    __shared__ float qsc[64], qsh[64], ksc[64], ksh[64];
    int tid = threadIdx.x;
    int b = blockIdx.x;
    int g = tid >> 5, lane = tid & 31;

    if (tid < 64) {
        int oq = 192 + tid;
        bn_params(d_psum[oq], d_psq[oq], 110592.f, gq[tid], bq[tid], qsc[tid], qsh[tid]);
        int ok = (tid >> 3) * 24 + (tid & 7);
        bn_params(d_psum[ok], d_psq[ok], 110592.f, gkv[ok], bkv[ok], ksc[tid], ksh[tid]);
    }
    __syncthreads();

    for (int idx = tid; idx < 64 * 48; idx += 256) {
        int c64 = idx / 48, h = idx % 48;
        int oq = 192 + c64;
        qs[c64 * 49 + h] = d_proj[oq * NHWD + b * 48 + h] * qsc[c64] + qsh[c64];
        int ok = (c64 >> 3) * 24 + (c64 & 7);
        ks[c64 * 49 + h] = d_proj[ok * NHWD + b * 48 + h] * ksc[c64] + ksh[c64];
    }
    for (int idx = tid; idx < 36 * 48; idx += 256) {
        int p = idx / 48, t = idx % 48;
        sW2q[p * 49 + t] = d_W2q[idx];
        sW2k[p * 49 + t] = d_W2k[idx];
    }
    for (int idx = tid; idx < 8 * 48; idx += 256) { sW1q[idx] = d_W1q[idx]; sW1k[idx] = d_W1k[idx]; }
    __syncthreads();

    float vsumqk = 0.f, vsqqk = 0.f, vtq = 0.f, vtk = 0.f, vsumqr = 0.f, vsumkr = 0.f;

    if (lane < 28) {
        int a, bb2; decode_pair(lane, a, bb2);
        const float* qa = &qs[(g * 8 + a) * 49];
        const float* qb = &qs[(g * 8 + bb2) * 49];
        const float* ka = &ks[(g * 8 + a) * 49];
        const float* kb = &ks[(g * 8 + bb2) * 49];
        const float* w2q = &sW2q[(8 + lane) * 49];
        const float* w2k = &sW2k[(8 + lane) * 49];
        float Qp = 0.f, Kp = 0.f, tq = 0.f, tk = 0.f;
        #pragma unroll 8
        for (int i = 0; i < 48; i++) {
            float qq = qa[i] * qb[i]; Qp += qq; tq = fmaf(qq, w2q[i], tq);
            float kk = ka[i] * kb[i]; Kp += kk; tk = fmaf(kk, w2k[i], tk);
        }
        vsqqk = 2.f * Qp * Kp;
        vtq = tq; vtk = tk;
    }
    if (lane < 8) {
        const float* qc = &qs[(g * 8 + lane) * 49];
        const float* kc = &ks[(g * 8 + lane) * 49];
        const float* w2q = &sW2q[lane * 49];
        const float* w2k = &sW2k[lane * 49];
        const float* w1q = &sW1q[lane * 48];
        const float* w1k = &sW1k[lane * 48];
        float Sq = 0.f, Sk = 0.f, Qd = 0.f, Kd = 0.f, tqd = 0.f, tkd = 0.f, sqr = 0.f, skr = 0.f;
        #pragma unroll 8
        for (int i = 0; i < 48; i++) {
            float qv = qc[i], kv = kc[i];
            Sq += qv; Sk += kv;
            float q2 = qv * qv, k2 = kv * kv;
            Qd += q2; Kd += k2;
            tqd = fmaf(q2, w2q[i], tqd);
            tkd = fmaf(k2, w2k[i], tkd);
            sqr = fmaf(qv, w1q[i], sqr);
            skr = fmaf(kv, w1k[i], skr);
        }
        vsumqk = Sq * Sk;
        vsqqk += Qd * Kd;
        vtq += tqd; vtk += tkd;
        vsumqr = sqr; vsumkr = skr;
    }
    #pragma unroll
    for (int off = 16; off; off >>= 1) {
        vsumqk += __shfl_xor_sync(0xffffffffu, vsumqk, off);
        vsqqk  += __shfl_xor_sync(0xffffffffu, vsqqk,  off);
        vtq    += __shfl_xor_sync(0xffffffffu, vtq,    off);
        vtk    += __shfl_xor_sync(0xffffffffu, vtk,    off);
        vsumqr += __shfl_xor_sync(0xffffffffu, vsumqr, off);
        vsumkr += __shfl_xor_sync(0xffffffffu, vsumkr, off);
    }
    if (lane == 0) {
        float fqr = fqr_p[0], fkr = fkr_p[0];
        atomicAdd(&d_ssum[g], vsumqk);
        atomicAdd(&d_ssq[g],  vsqqk);
        atomicAdd(&d_ssum[8 + g], fqr * vsumqr);
        atomicAdd(&d_ssq[8 + g],  fqr * fqr * vtq);
        atomicAdd(&d_ssum[16 + g], fkr * vsumkr);
        atomicAdd(&d_ssq[16 + g],  fkr * fkr * vtk);
    }
}

// ------- pass 3: logits + softmax + sv/sve (all BN params inlined) ---------
__global__ __launch_bounds__(128) void k_attn(const float* __restrict__ rel,
                       const float* __restrict__ fqr_p, const float* __restrict__ fkr_p,
                       const float* __restrict__ fsv_p, const float* __restrict__ fsve_p,
                       const float* __restrict__ gkv, const float* __restrict__ bkv,
                       const float* __restrict__ gq,  const float* __restrict__ bq,
                       const float* __restrict__ gsim) {
    __shared__ float sqA[8][48], sqR[8][48], skR[8][48], svs[16][48];
    __shared__ float srq[8][96], srk[8][96], sveS[16][97];
    __shared__ float S[2304];           // logits; later reused as 32x49 staging
    __shared__ float sst[64];
    __shared__ float psc[32], psh[32];
    int tid = threadIdx.x;
    int b = blockIdx.x >> 3, g = blockIdx.x & 7;
    if (tid < 64) sst[tid] = 0.f;

    float fqr = fqr_p[0], fkr = fkr_p[0], fsv = fsv_p[0], fsve = fsve_p[0];

    // sim BN scales (per-thread, redundant; shift dropped — softmax invariant)
    float ca, cb, cc2;
    {
        float n2 = 5308416.f, m, v;
        m = d_ssum[g] / n2;      v = d_ssq[g] / n2 - m * m;      ca  = rsqrtf(v + EPSV) * gsim[g];
        m = d_ssum[8 + g] / n2;  v = d_ssq[8 + g] / n2 - m * m;  cb  = rsqrtf(v + EPSV) * gsim[8 + g]  * fqr;
        m = d_ssum[16 + g] / n2; v = d_ssq[16 + g] / n2 - m * m; cc2 = rsqrtf(v + EPSV) * gsim[16 + g] * fkr;
    }
    // proj BN params for the 32 channels this block uses
    if (tid < 32) {
        int o; float gamma, beta;
        if (tid < 8)       { o = 192 + g * 8 + tid;      gamma = gq[o - 192];  beta = bq[o - 192]; }
        else if (tid < 16) { o = g * 24 + (tid - 8);     gamma = gkv[o];       beta = bkv[o]; }
        else               { o = g * 24 + 8 + (tid - 16);gamma = gkv[o];       beta = bkv[o]; }
        bn_params(d_psum[o], d_psq[o], 110592.f, gamma, beta, psc[tid], psh[tid]);
    }
    __syncthreads();

    for (int idx = tid; idx < 384; idx += 128) {
        int c = idx / 48, h = idx % 48;
        float qv = d_proj[(192 + g * 8 + c) * NHWD + b * 48 + h] * psc[c] + psh[c];
        sqR[c][h] = qv;
        sqA[c][h] = ca * qv;
        skR[c][h] = d_proj[(g * 24 + c) * NHWD + b * 48 + h] * psc[8 + c] + psh[8 + c];
    }
    for (int idx = tid; idx < 768; idx += 128) {
        int c = idx / 48, h = idx % 48;
        svs[c][h] = fsv * (d_proj[(g * 24 + 8 + c) * NHWD + b * 48 + h] * psc[16 + c] + psh[16 + c]);
    }
    for (int idx = tid; idx < 32 * 95; idx += 128) {
        int r = idx / 95, d = idx % 95;
        float v = rel[idx];
        if (r < 8)       srq[r][d]          = cb  * v;
        else if (r < 16) srk[r - 8][d]      = cc2 * v;
        else             sveS[r - 16][d + 1] = fsve * v;
    }
    __syncthreads();

    int c0 = (tid & 7) * 2, i0 = (tid >> 3) * 3;
    int j0 = (tid & 7) * 6;

    // Phase A: fused logits
    {
        float L[18];
        #pragma unroll
        for (int e = 0; e < 18; e++) L[e] = 0.f;
        #pragma unroll
        for (int c = 0; c < 8; c++) {
            float qa[3], qr[3], kv[6], rqv[8], rkv[8];
            #pragma unroll
            for (int di = 0; di < 3; di++) { qa[di] = sqA[c][i0 + di]; qr[di] = sqR[c][i0 + di]; }
            #pragma unroll
            for (int dj = 0; dj < 6; dj++) kv[dj] = skR[c][j0 + dj];
            const float* rqp = &srq[c][0] + (i0 - j0 + 42);
            const float* rkp = &srk[c][0] + (j0 - i0 + 45);
            #pragma unroll
            for (int t = 0; t < 8; t++) { rqv[t] = rqp[t]; rkv[t] = rkp[t]; }
            #pragma unroll
            for (int di = 0; di < 3; di++)
                #pragma unroll
                for (int dj = 0; dj < 6; dj++) {
                    int e = di * 6 + dj;
                    L[e] = fmaf(kv[dj], qa[di],            L[e]);
                    L[e] = fmaf(kv[dj], rkv[dj + 2 - di],  L[e]);
                    L[e] = fmaf(qr[di], rqv[di + 5 - dj],  L[e]);
                }
        }
        #pragma unroll
        for (int di = 0; di < 3; di++)
            #pragma unroll
            for (int dj = 0; dj < 6; dj++)
                S[(i0 + di) * 48 + (j0 + dj)] = L[di * 6 + dj];
    }
    __syncthreads();

    // Phase B: softmax rows
    {
        int w = tid >> 5, lane = tid & 31;
        for (int t = 0; t < 12; t++) {
            int r = w * 12 + t;
            float v0 = S[r * 48 + lane];
            float v1 = (lane < 16) ? S[r * 48 + 32 + lane] : -1e30f;
            float m = fmaxf(v0, v1);
            #pragma unroll
            for (int off = 16; off; off >>= 1) m = fmaxf(m, __shfl_xor_sync(0xffffffffu, m, off));
            float e0 = __expf(v0 - m);
            float e1 = (lane < 16) ? __expf(v1 - m) : 0.f;
            float s = e0 + e1;
            #pragma unroll
            for (int off = 16; off; off >>= 1) s += __shfl_xor_sync(0xffffffffu, s, off);
            float inv = 1.f / s;
            S[r * 48 + lane] = e0 * inv;
            if (lane < 16) S[r * 48 + 32 + lane] = e1 * inv;
        }
    }
    __syncthreads();

    // Phase C: sv + sve with sliding ve windows and float4 S/v reads
    float svv[2][3] = {{0.f,0.f,0.f},{0.f,0.f,0.f}};
    float sev[2][3] = {{0.f,0.f,0.f},{0.f,0.f,0.f}};
    {
        const float* Sr0 = &S[i0 * 48];
        const float* Sr1 = &S[(i0 + 1) * 48];
        const float* Sr2 = &S[(i0 + 2) * 48];
        const float* vp0 = &svs[c0][0];
        const float* vp1 = &svs[c0 + 1][0];
        const float* ve0 = &sveS[c0][1];
        const float* ve1 = &sveS[c0 + 1][1];
        float wa0 = ve0[i0 + 47], wa1 = ve0[i0 + 48], wa2 = ve0[i0 + 49];
        float wb0 = ve1[i0 + 47], wb1 = ve1[i0 + 48], wb2 = ve1[i0 + 49];
        #pragma unroll
        for (int jo = 0; jo < 12; jo++) {
            float4 s0q = *(const float4*)(Sr0 + jo * 4);
            float4 s1q = *(const float4*)(Sr1 + jo * 4);
            float4 s2q = *(const float4*)(Sr2 + jo * 4);
            float4 v0q = *(const float4*)(vp0 + jo * 4);
            float4 v1q = *(const float4*)(vp1 + jo * 4);
            #pragma unroll
            for (int jj = 0; jj < 4; jj++) {
                int j = jo * 4 + jj;
                float sa = (jj == 0) ? s0q.x : (jj == 1) ? s0q.y : (jj == 2) ? s0q.z : s0q.w;
                float sb = (jj == 0) ? s1q.x : (jj == 1) ? s1q.y : (jj == 2) ? s1q.z : s1q.w;
                float sc = (jj == 0) ? s2q.x : (jj == 1) ? s2q.y : (jj == 2) ? s2q.z : s2q.w;
                float va = (jj == 0) ? v0q.x : (jj == 1) ? v0q.y : (jj == 2) ? v0q.z : v0q.w;
                float vb = (jj == 0) ? v1q.x : (jj == 1) ? v1q.y : (jj == 2) ? v1q.z : v1q.w;
                svv[0][0] = fmaf(sa, va, svv[0][0]);
                svv[0][1] = fmaf(sb, va, svv[0][1]);
                svv[0][2] = fmaf(sc, va, svv[0][2]);
                svv[1][0] = fmaf(sa, vb, svv[1][0]);
                svv[1][1] = fmaf(sb, vb, svv[1][1]);
                svv[1][2] = fmaf(sc, vb, svv[1][2]);
                sev[0][0] = fmaf(sa, wa0, sev[0][0]);
                sev[0][1] = fmaf(sb, wa1, sev[0][1]);
                sev[0][2] = fmaf(sc, wa2, sev[0][2]);
                sev[1][0] = fmaf(sa, wb0, sev[1][0]);
                sev[1][1] = fmaf(sb, wb1, sev[1][1]);
                sev[1][2] = fmaf(sc, wb2, sev[1][2]);
                wa2 = wa1; wa1 = wa0; wa0 = ve0[i0 + 46 - j];
                wb2 = wb1; wb1 = wb0; wb0 = ve1[i0 + 46 - j];
            }
        }
    }

    // out-BN stats: register reduce across the 4 threads sharing (c0) per warp pair set
    {
        float r8[8];
        #pragma unroll
        for (int cl = 0; cl < 2; cl++) {
            float s1 = svv[cl][0] + svv[cl][1] + svv[cl][2];
            float q1 = svv[cl][0]*svv[cl][0] + svv[cl][1]*svv[cl][1] + svv[cl][2]*svv[cl][2];
            float s2 = sev[cl][0] + sev[cl][1] + sev[cl][2];
            float q2 = sev[cl][0]*sev[cl][0] + sev[cl][1]*sev[cl][1] + sev[cl][2]*sev[cl][2];
            r8[cl*4+0] = s1; r8[cl*4+1] = q1; r8[cl*4+2] = s2; r8[cl*4+3] = q2;
        }
        #pragma unroll
        for (int k = 0; k < 8; k++) {
            r8[k] += __shfl_xor_sync(0xffffffffu, r8[k], 8);
            r8[k] += __shfl_xor_sync(0xffffffffu, r8[k], 16);
        }
        if ((tid & 31) < 8) {
            #pragma unroll
            for (int cl = 0; cl < 2; cl++) {
                int o_sv = (c0 + cl) * 2;      // local sv channel; sve = +1
                atomicAdd(&sst[o_sv],          r8[cl*4+0]);
                atomicAdd(&sst[32 + o_sv],     r8[cl*4+1]);
                atomicAdd(&sst[o_sv + 1],      r8[cl*4+2]);
                atomicAdd(&sst[32 + o_sv + 1], r8[cl*4+3]);
            }
        }
    }
    __syncthreads();   // all S reads done; sst atomics drained

    // stage results into S region (32 x 49 padded), then coalesced copy out
    {
        float* ob = S;
        #pragma unroll
        for (int cl = 0; cl < 2; cl++) {
            int c = c0 + cl;
            ob[(c*2)*49 + i0 + 0] = svv[cl][0];
            ob[(c*2)*49 + i0 + 1] = svv[cl][1];
            ob[(c*2)*49 + i0 + 2] = svv[cl][2];
            ob[(c*2+1)*49 + i0 + 0] = sev[cl][0];
            ob[(c*2+1)*49 + i0 + 1] = sev[cl][1];
            ob[(c*2+1)*49 + i0 + 2] = sev[cl][2];
        }
    }
    __syncthreads();
    {
        float* dst = d_outpre + (size_t)b * 12288 + g * 1536;
        #pragma unroll
        for (int t = 0; t < 12; t++) {
            int idx = t * 128 + tid;
            dst[idx] = S[(idx / 48) * 49 + idx % 48];
        }
        if (tid < 32) {
            atomicAdd(&d_osum[g * 32 + tid], sst[tid]);
            atomicAdd(&d_osq[g * 32 + tid],  sst[32 + tid]);
        }
    }
}

// ------- pass 4: out BN (inlined) + s-pair sum + transpose -----------------
__global__ void k_out(float* __restrict__ out,
                      const float* __restrict__ gout, const float* __restrict__ bout) {
    __shared__ float tile[48 * 49];
    int tid = threadIdx.x;
    int w = blockIdx.x % 48, gc = blockIdx.x / 48;
    int o0 = gc * 2, o1 = o0 + 1;
    float s0, sh0, s1, sh1;
    bn_params(d_osum[o0], d_osq[o0], 110592.f, gout[o0], bout[o0], s0, sh0);
    bn_params(d_osum[o1], d_osq[o1], 110592.f, gout[o1], bout[o1], s1, sh1);
    float sh = sh0 + sh1;
    #pragma unroll
    for (int t = 0; t < 9; t++) {
        int idx = t * 256 + tid;
        int d = idx / 48, h = idx % 48;
        int bb = w * 48 + d;
        float v = d_outpre[bb * 12288 + o0 * 48 + h] * s0
                + d_outpre[bb * 12288 + o1 * 48 + h] * s1 + sh;
        tile[h * 49 + d] = v;
    }
    __syncthreads();
    #pragma unroll
    for (int t = 0; t < 9; t++) {
        int idx = t * 256 + tid;
        int h = idx / 48, d = idx % 48;
        out[gc * NHWD + h * 2304 + w * 48 + d] = tile[h * 49 + d];
    }
}

// ---------------------------------------------------------------------------
extern "C" void kernel_launch(void* const* d_in, const int* in_sizes, int n_in,
                              void* d_out, int out_size) {
    const float* x    = (const float*)d_in[0];
    const float* Wkv  = (const float*)d_in[1];
    const float* Wq   = (const float*)d_in[2];
    const float* gkv  = (const float*)d_in[3];
    const float* bkv  = (const float*)d_in[4];
    const float* gq   = (const float*)d_in[5];
    const float* bq   = (const float*)d_in[6];
    const float* gsim = (const float*)d_in[7];
    const float* bsim = (const float*)d_in[8];   // shift dropped (softmax invariant)
    const float* gout = (const float*)d_in[9];
    const float* bout = (const float*)d_in[10];
    const float* rel  = (const float*)d_in[11];
    const float* fqr  = (const float*)d_in[12];
    const float* fkr  = (const float*)d_in[13];
    const float* fsv  = (const float*)d_in[14];
    const float* fsve = (const float*)d_in[15];
    (void)bsim;
    float* out = (float*)d_out;

    const int proj_smem = (256 * 65 + 64 * 64) * (int)sizeof(float);
    cudaFuncSetAttribute(k_proj, cudaFuncAttributeMaxDynamicSharedMemorySize, proj_smem);

    k_pre<<<4, 256>>>(rel);
    k_proj<<<1728, 256, proj_smem>>>(x, Wkv, Wq);
    k_simstat2<<<2304, 256>>>(fqr, fkr, gkv, bkv, gq, bq);
    k_attn<<<18432, 128>>>(rel, fqr, fkr, fsv, fsve, gkv, bkv, gq, bq, gsim);
    k_out<<<6144, 256>>>(out, gout, bout);
}

// round 7
// speedup vs baseline: 1.5732x; 1.0823x over previous
#include <cuda_runtime.h>
#include <math.h>

#define H48   48
#define NG    8
#define NC    64
#define NB    2304
#define NHWD  110592
#define NOC   256
#define EPSV  1e-5f

// ---------------- scratch ----------------
__device__ float d_proj[NOC * NHWD];        // [o][b*48 + h]
__device__ float d_outpre[NB * NOC * H48];  // [b][g*1536 + o_local*48 + i]
__device__ float d_psum[NOC], d_psq[NOC];
__device__ float d_ssum[24],  d_ssq[24];
__device__ float d_osum[NOC], d_osq[NOC];
__device__ float d_W1q[8 * 48], d_W1k[8 * 48];
__device__ float d_W2q[36 * 48], d_W2k[36 * 48];

__device__ __forceinline__ void decode_pair(int op, int& a, int& b) {
    a = 0; int r = op;
    while (r >= 7 - a) { r -= 7 - a; a++; }
    b = a + 1 + r;
}

// ------------- pass 0: zero accumulators + rel window tables --------------
__global__ void k_pre(const float* __restrict__ rel) {
    int tid = threadIdx.x;
    if (blockIdx.x == 0) {
        if (tid < NOC) { d_psum[tid] = 0.f; d_psq[tid] = 0.f; d_osum[tid] = 0.f; d_osq[tid] = 0.f; }
        if (tid < 24)  { d_ssum[tid] = 0.f; d_ssq[tid]  = 0.f; }
        for (int idx = tid; idx < 16 * 48; idx += 256) {
            int r = idx / 48, t = idx % 48;
            float s = 0.f;
            for (int d = 0; d < 48; d++) s += rel[r * 95 + t + d];
            if (r < 8) d_W1q[r * 48 + t] = s; else d_W1k[(r - 8) * 48 + t] = s;
        }
    } else {
        for (int idx = tid; idx < 24 * 48; idx += 256) {
            int u = (blockIdx.x - 1) * 24 + idx / 48, t = idx % 48;
            int side = u / 36, p = u % 36;
            int a, b; float f;
            if (p < 8) { a = p; b = p; f = 1.f; } else { decode_pair(p - 8, a, b); f = 2.f; }
            const float* ra = rel + (side * 8 + a) * 95;
            const float* rb = rel + (side * 8 + b) * 95;
            float s = 0.f;
            for (int d = 0; d < 48; d++) s = fmaf(ra[t + d], rb[t + d], s);
            s *= f;
            if (side == 0) d_W2q[p * 48 + t] = s; else d_W2k[p * 48 + t] = s;
        }
    }
}

// ---------------- pass 1: projection GEMM + per-channel stats --------------
__global__ void k_proj(const float* __restrict__ x,
                       const float* __restrict__ Wkv,
                       const float* __restrict__ Wq) {
    extern __shared__ float sm[];
    float* Ws = sm;              // 256 x 65
    float* Xs = sm + 256 * 65;   // 64 x 64
    int tid = threadIdx.x;
    int bt = blockIdx.x % 288, ht = blockIdx.x / 288;
    int b0 = bt * 8, h0 = ht * 8;

    for (int idx = tid; idx < 256 * 64; idx += 256) {
        int o = idx >> 6, c = idx & 63;
        Ws[o * 65 + c] = (o < 192) ? Wkv[o * 64 + c] : Wq[(o - 192) * 64 + c];
    }
    #pragma unroll
    for (int t = 0; t < 16; t++) {
        int idx = t * 256 + tid;
        int c = idx >> 6, sp = idx & 63;
        int hl = sp >> 3, bl = sp & 7;
        Xs[c * 64 + sp] = x[c * NHWD + (h0 + hl) * 2304 + b0 + bl];
    }
    __syncthreads();

    int og = tid >> 3, bl = tid & 7;
    float acc[8][8];
    #pragma unroll
    for (int i = 0; i < 8; i++)
        #pragma unroll
        for (int h = 0; h < 8; h++) acc[i][h] = 0.f;

    #pragma unroll 4
    for (int c = 0; c < 64; c++) {
        float xv[8];
        #pragma unroll
        for (int hl = 0; hl < 8; hl++) xv[hl] = Xs[c * 64 + hl * 8 + bl];
        #pragma unroll
        for (int i = 0; i < 8; i++) {
            float wv = Ws[(og * 8 + i) * 65 + c];
            #pragma unroll
            for (int hl = 0; hl < 8; hl++) acc[i][hl] = fmaf(wv, xv[hl], acc[i][hl]);
        }
    }

    #pragma unroll
    for (int i = 0; i < 8; i++) {
        int o = og * 8 + i;
        float s = 0.f, q = 0.f;
        #pragma unroll
        for (int hl = 0; hl < 8; hl++) { float v = acc[i][hl]; s += v; q += v * v; }
        float* base = d_proj + o * NHWD + (b0 + bl) * 48 + h0;
        *(float4*)(base)     = make_float4(acc[i][0], acc[i][1], acc[i][2], acc[i][3]);
        *(float4*)(base + 4) = make_float4(acc[i][4], acc[i][5], acc[i][6], acc[i][7]);
        s += __shfl_down_sync(0xffffffffu, s, 4, 8);
        s += __shfl_down_sync(0xffffffffu, s, 2, 8);
        s += __shfl_down_sync(0xffffffffu, s, 1, 8);
        q += __shfl_down_sync(0xffffffffu, q, 4, 8);
        q += __shfl_down_sync(0xffffffffu, q, 2, 8);
        q += __shfl_down_sync(0xffffffffu, q, 1, 8);
        if (bl == 0) { atomicAdd(&d_psum[o], s); atomicAdd(&d_psq[o], q); }
    }
}

__device__ __forceinline__ void bn_params(float sum, float sq, float n, float gamma, float beta,
                                          float& sc, float& sh) {
    float m = sum / n;
    float var = sq / n - m * m;
    sc = rsqrtf(var + EPSV) * gamma;
    sh = beta - m * sc;
}

// ------------- pass 2: sim BN stats via Gram factorization -----------------
__global__ __launch_bounds__(256) void k_simstat2(const float* __restrict__ fqr_p,
                                                  const float* __restrict__ fkr_p,
                                                  const float* __restrict__ gkv, const float* __restrict__ bkv,
                                                  const float* __restrict__ gq,  const float* __restrict__ bq) {
    __shared__ float qs[64 * 49], ks[64 * 49];
    __shared__ float sW2q[36 * 49], sW2k[36 * 49];
    __shared__ float sW1q[8 * 48], sW1k[8 * 48];
    __shared__ float qsc[64], qsh[64], ksc[64], ksh[64];
    int tid = threadIdx.x;
    int b = blockIdx.x;
    int g = tid >> 5, lane = tid & 31;

    if (tid < 64) {
        int oq = 192 + tid;
        bn_params(d_psum[oq], d_psq[oq], 110592.f, gq[tid], bq[tid], qsc[tid], qsh[tid]);
        int ok = (tid >> 3) * 24 + (tid & 7);
        bn_params(d_psum[ok], d_psq[ok], 110592.f, gkv[ok], bkv[ok], ksc[tid], ksh[tid]);
    }
    __syncthreads();

    for (int idx = tid; idx < 64 * 48; idx += 256) {
        int c64 = idx / 48, h = idx % 48;
        int oq = 192 + c64;
        qs[c64 * 49 + h] = d_proj[oq * NHWD + b * 48 + h] * qsc[c64] + qsh[c64];
        int ok = (c64 >> 3) * 24 + (c64 & 7);
        ks[c64 * 49 + h] = d_proj[ok * NHWD + b * 48 + h] * ksc[c64] + ksh[c64];
    }
    for (int idx = tid; idx < 36 * 48; idx += 256) {
        int p = idx / 48, t = idx % 48;
        sW2q[p * 49 + t] = d_W2q[idx];
        sW2k[p * 49 + t] = d_W2k[idx];
    }
    for (int idx = tid; idx < 8 * 48; idx += 256) { sW1q[idx] = d_W1q[idx]; sW1k[idx] = d_W1k[idx]; }
    __syncthreads();

    float vsumqk = 0.f, vsqqk = 0.f, vtq = 0.f, vtk = 0.f, vsumqr = 0.f, vsumkr = 0.f;

    if (lane < 28) {
        int a, bb2; decode_pair(lane, a, bb2);
        const float* qa = &qs[(g * 8 + a) * 49];
        const float* qb = &qs[(g * 8 + bb2) * 49];
        const float* ka = &ks[(g * 8 + a) * 49];
        const float* kb = &ks[(g * 8 + bb2) * 49];
        const float* w2q = &sW2q[(8 + lane) * 49];
        const float* w2k = &sW2k[(8 + lane) * 49];
        float Qp = 0.f, Kp = 0.f, tq = 0.f, tk = 0.f;
        #pragma unroll 8
        for (int i = 0; i < 48; i++) {
            float qq = qa[i] * qb[i]; Qp += qq; tq = fmaf(qq, w2q[i], tq);
            float kk = ka[i] * kb[i]; Kp += kk; tk = fmaf(kk, w2k[i], tk);
        }
        vsqqk = 2.f * Qp * Kp;
        vtq = tq; vtk = tk;
    }
    if (lane < 8) {
        const float* qc = &qs[(g * 8 + lane) * 49];
        const float* kc = &ks[(g * 8 + lane) * 49];
        const float* w2q = &sW2q[lane * 49];
        const float* w2k = &sW2k[lane * 49];
        const float* w1q = &sW1q[lane * 48];
        const float* w1k = &sW1k[lane * 48];
        float Sq = 0.f, Sk = 0.f, Qd = 0.f, Kd = 0.f, tqd = 0.f, tkd = 0.f, sqr = 0.f, skr = 0.f;
        #pragma unroll 8
        for (int i = 0; i < 48; i++) {
            float qv = qc[i], kv = kc[i];
            Sq += qv; Sk += kv;
            float q2 = qv * qv, k2 = kv * kv;
            Qd += q2; Kd += k2;
            tqd = fmaf(q2, w2q[i], tqd);
            tkd = fmaf(k2, w2k[i], tkd);
            sqr = fmaf(qv, w1q[i], sqr);
            skr = fmaf(kv, w1k[i], skr);
        }
        vsumqk = Sq * Sk;
        vsqqk += Qd * Kd;
        vtq += tqd; vtk += tkd;
        vsumqr = sqr; vsumkr = skr;
    }
    #pragma unroll
    for (int off = 16; off; off >>= 1) {
        vsumqk += __shfl_xor_sync(0xffffffffu, vsumqk, off);
        vsqqk  += __shfl_xor_sync(0xffffffffu, vsqqk,  off);
        vtq    += __shfl_xor_sync(0xffffffffu, vtq,    off);
        vtk    += __shfl_xor_sync(0xffffffffu, vtk,    off);
        vsumqr += __shfl_xor_sync(0xffffffffu, vsumqr, off);
        vsumkr += __shfl_xor_sync(0xffffffffu, vsumkr, off);
    }
    if (lane == 0) {
        float fqr = fqr_p[0], fkr = fkr_p[0];
        atomicAdd(&d_ssum[g], vsumqk);
        atomicAdd(&d_ssq[g],  vsqqk);
        atomicAdd(&d_ssum[8 + g], fqr * vsumqr);
        atomicAdd(&d_ssq[8 + g],  fqr * fqr * vtq);
        atomicAdd(&d_ssum[16 + g], fkr * vsumkr);
        atomicAdd(&d_ssq[16 + g],  fkr * fkr * vtk);
    }
}

// ------- pass 3: logits + softmax + sv/sve (smem overlay, 22KB) ------------
// smem layout (floats):
//   S    [0, 2304)                logits; later 32x49 output staging
//   sq   [2304, 2688)  8x48       raw BN'd q
//   sk   [2688, 3072)  8x48       raw BN'd k
//   D    [3072, 5392)  2320:
//        Phase A: srq = D+0 (8x96, cb-scaled), srk = D+768 (8x96, cc-scaled)
//        Phase C: svs = D+0 (16x48, fsv-scaled), sveS = D+768 (16x97, fsve, +1 off)
//   sst  [5392, 5456)
//   psc  [5456, 5488)  psh [5488, 5520)
__global__ __launch_bounds__(128, 8) void k_attn(const float* __restrict__ rel,
                       const float* __restrict__ fqr_p, const float* __restrict__ fkr_p,
                       const float* __restrict__ fsv_p, const float* __restrict__ fsve_p,
                       const float* __restrict__ gkv, const float* __restrict__ bkv,
                       const float* __restrict__ gq,  const float* __restrict__ bq,
                       const float* __restrict__ gsim) {
    __shared__ __align__(16) float sm[5520];
    float* S   = sm;
    float* sq  = sm + 2304;
    float* sk  = sm + 2688;
    float* D   = sm + 3072;
    float* sst = sm + 5392;
    float* psc = sm + 5456;
    float* psh = sm + 5488;

    int tid = threadIdx.x;
    int b = blockIdx.x >> 3, g = blockIdx.x & 7;
    if (tid < 64) sst[tid] = 0.f;

    float fqr = fqr_p[0], fkr = fkr_p[0], fsv = fsv_p[0], fsve = fsve_p[0];

    // sim BN scales (redundant per-thread; shift dropped — softmax invariant)
    float ca, cb, cc2;
    {
        float n2 = 5308416.f, m, v;
        m = d_ssum[g] / n2;      v = d_ssq[g] / n2 - m * m;      ca  = rsqrtf(v + EPSV) * gsim[g];
        m = d_ssum[8 + g] / n2;  v = d_ssq[8 + g] / n2 - m * m;  cb  = rsqrtf(v + EPSV) * gsim[8 + g]  * fqr;
        m = d_ssum[16 + g] / n2; v = d_ssq[16 + g] / n2 - m * m; cc2 = rsqrtf(v + EPSV) * gsim[16 + g] * fkr;
    }
    if (tid < 32) {
        int o; float gamma, beta;
        if (tid < 8)       { o = 192 + g * 8 + tid;       gamma = gq[o - 192];  beta = bq[o - 192]; }
        else if (tid < 16) { o = g * 24 + (tid - 8);      gamma = gkv[o];       beta = bkv[o]; }
        else               { o = g * 24 + 8 + (tid - 16); gamma = gkv[o];       beta = bkv[o]; }
        bn_params(d_psum[o], d_psq[o], 110592.f, gamma, beta, psc[tid], psh[tid]);
    }
    __syncthreads();

    // load q, k (raw BN'd) + scaled rel rows into D
    for (int idx = tid; idx < 384; idx += 128) {
        int c = idx / 48, h = idx % 48;
        sq[idx] = d_proj[(192 + g * 8 + c) * NHWD + b * 48 + h] * psc[c] + psh[c];
        sk[idx] = d_proj[(g * 24 + c) * NHWD + b * 48 + h] * psc[8 + c] + psh[8 + c];
    }
    for (int idx = tid; idx < 16 * 95; idx += 128) {
        int r = idx / 95, d = idx % 95;
        float v = rel[idx];
        if (r < 8) D[r * 96 + d]         = cb  * v;     // srq
        else       D[768 + (r-8)*96 + d] = cc2 * v;     // srk
    }
    __syncthreads();

    int c0 = (tid & 7) * 2, i0 = (tid >> 3) * 3;
    int j0 = (tid & 7) * 6;

    // Phase A: fused logits (qa = ca*q in registers; kv via float2)
    {
        float L[18];
        #pragma unroll
        for (int e = 0; e < 18; e++) L[e] = 0.f;
        #pragma unroll
        for (int c = 0; c < 8; c++) {
            float qr[3], qa[3], kv[6], rqv[8], rkv[8];
            #pragma unroll
            for (int di = 0; di < 3; di++) { qr[di] = sq[c * 48 + i0 + di]; qa[di] = ca * qr[di]; }
            float2 kv01 = *(const float2*)(sk + c * 48 + j0);
            float2 kv23 = *(const float2*)(sk + c * 48 + j0 + 2);
            float2 kv45 = *(const float2*)(sk + c * 48 + j0 + 4);
            kv[0] = kv01.x; kv[1] = kv01.y; kv[2] = kv23.x;
            kv[3] = kv23.y; kv[4] = kv45.x; kv[5] = kv45.y;
            const float* rqp = D + c * 96 + (i0 - j0 + 42);
            const float* rkp = D + 768 + c * 96 + (j0 - i0 + 45);
            #pragma unroll
            for (int t = 0; t < 8; t++) { rqv[t] = rqp[t]; rkv[t] = rkp[t]; }
            #pragma unroll
            for (int di = 0; di < 3; di++)
                #pragma unroll
                for (int dj = 0; dj < 6; dj++) {
                    int e = di * 6 + dj;
                    L[e] = fmaf(kv[dj], qa[di],            L[e]);
                    L[e] = fmaf(kv[dj], rkv[dj + 2 - di],  L[e]);
                    L[e] = fmaf(qr[di], rqv[di + 5 - dj],  L[e]);
                }
        }
        #pragma unroll
        for (int di = 0; di < 3; di++)
            #pragma unroll
            for (int dj = 0; dj < 6; dj++)
                S[(i0 + di) * 48 + (j0 + dj)] = L[di * 6 + dj];
    }
    __syncthreads();   // Phase A done: S valid, D region free

    // overwrite D with Phase C data (LDG latency hides behind softmax below)
    for (int idx = tid; idx < 768; idx += 128) {
        int c = idx / 48, h = idx % 48;
        D[idx] = fsv * (d_proj[(g * 24 + 8 + c) * NHWD + b * 48 + h] * psc[16 + c] + psh[16 + c]);
    }
    for (int idx = tid; idx < 16 * 95; idx += 128) {
        int r = idx / 95, d = idx % 95;
        D[768 + r * 97 + d + 1] = fsve * rel[(16 + r) * 95 + d];
    }

    // Phase B: softmax, one row per 16-lane half-warp (3 values per lane)
    {
        int w = tid >> 5, hw = (tid >> 4) & 1, hl = tid & 15;
        for (int t = 0; t < 6; t++) {
            int r = w * 12 + t * 2 + hw;
            float a = S[r * 48 + hl];
            float b2 = S[r * 48 + 16 + hl];
            float c3 = S[r * 48 + 32 + hl];
            float m = fmaxf(a, fmaxf(b2, c3));
            #pragma unroll
            for (int off = 8; off; off >>= 1) m = fmaxf(m, __shfl_xor_sync(0xffffffffu, m, off));
            float ea = __expf(a - m), eb = __expf(b2 - m), ec = __expf(c3 - m);
            float s = ea + eb + ec;
            #pragma unroll
            for (int off = 8; off; off >>= 1) s += __shfl_xor_sync(0xffffffffu, s, off);
            float inv = 1.f / s;
            S[r * 48 + hl]      = ea * inv;
            S[r * 48 + 16 + hl] = eb * inv;
            S[r * 48 + 32 + hl] = ec * inv;
        }
    }
    __syncthreads();

    // Phase C: sv + sve with sliding ve windows and float4 S/v reads
    float svv[2][3] = {{0.f,0.f,0.f},{0.f,0.f,0.f}};
    float sev[2][3] = {{0.f,0.f,0.f},{0.f,0.f,0.f}};
    {
        const float* Sr0 = &S[i0 * 48];
        const float* Sr1 = &S[(i0 + 1) * 48];
        const float* Sr2 = &S[(i0 + 2) * 48];
        const float* vp0 = D + c0 * 48;
        const float* vp1 = D + (c0 + 1) * 48;
        const float* ve0 = D + 768 + c0 * 97 + 1;
        const float* ve1 = D + 768 + (c0 + 1) * 97 + 1;
        float wa0 = ve0[i0 + 47], wa1 = ve0[i0 + 48], wa2 = ve0[i0 + 49];
        float wb0 = ve1[i0 + 47], wb1 = ve1[i0 + 48], wb2 = ve1[i0 + 49];
        #pragma unroll
        for (int jo = 0; jo < 12; jo++) {
            float4 s0q = *(const float4*)(Sr0 + jo * 4);
            float4 s1q = *(const float4*)(Sr1 + jo * 4);
            float4 s2q = *(const float4*)(Sr2 + jo * 4);
            float4 v0q = *(const float4*)(vp0 + jo * 4);
            float4 v1q = *(const float4*)(vp1 + jo * 4);
            #pragma unroll
            for (int jj = 0; jj < 4; jj++) {
                int j = jo * 4 + jj;
                float sa = (jj == 0) ? s0q.x : (jj == 1) ? s0q.y : (jj == 2) ? s0q.z : s0q.w;
                float sb = (jj == 0) ? s1q.x : (jj == 1) ? s1q.y : (jj == 2) ? s1q.z : s1q.w;
                float sc = (jj == 0) ? s2q.x : (jj == 1) ? s2q.y : (jj == 2) ? s2q.z : s2q.w;
                float va = (jj == 0) ? v0q.x : (jj == 1) ? v0q.y : (jj == 2) ? v0q.z : v0q.w;
                float vb = (jj == 0) ? v1q.x : (jj == 1) ? v1q.y : (jj == 2) ? v1q.z : v1q.w;
                svv[0][0] = fmaf(sa, va, svv[0][0]);
                svv[0][1] = fmaf(sb, va, svv[0][1]);
                svv[0][2] = fmaf(sc, va, svv[0][2]);
                svv[1][0] = fmaf(sa, vb, svv[1][0]);
                svv[1][1] = fmaf(sb, vb, svv[1][1]);
                svv[1][2] = fmaf(sc, vb, svv[1][2]);
                sev[0][0] = fmaf(sa, wa0, sev[0][0]);
                sev[0][1] = fmaf(sb, wa1, sev[0][1]);
                sev[0][2] = fmaf(sc, wa2, sev[0][2]);
                sev[1][0] = fmaf(sa, wb0, sev[1][0]);
                sev[1][1] = fmaf(sb, wb1, sev[1][1]);
                sev[1][2] = fmaf(sc, wb2, sev[1][2]);
                wa2 = wa1; wa1 = wa0; wa0 = ve0[i0 + 46 - j];
                wb2 = wb1; wb1 = wb0; wb0 = ve1[i0 + 46 - j];
            }
        }
    }

    // out-BN stats: register reduce across the 4 threads sharing c0
    {
        float r8[8];
        #pragma unroll
        for (int cl = 0; cl < 2; cl++) {
            float s1 = svv[cl][0] + svv[cl][1] + svv[cl][2];
            float q1 = svv[cl][0]*svv[cl][0] + svv[cl][1]*svv[cl][1] + svv[cl][2]*svv[cl][2];
            float s2 = sev[cl][0] + sev[cl][1] + sev[cl][2];
            float q2 = sev[cl][0]*sev[cl][0] + sev[cl][1]*sev[cl][1] + sev[cl][2]*sev[cl][2];
            r8[cl*4+0] = s1; r8[cl*4+1] = q1; r8[cl*4+2] = s2; r8[cl*4+3] = q2;
        }
        #pragma unroll
        for (int k = 0; k < 8; k++) {
            r8[k] += __shfl_xor_sync(0xffffffffu, r8[k], 8);
            r8[k] += __shfl_xor_sync(0xffffffffu, r8[k], 16);
        }
        if ((tid & 31) < 8) {
            #pragma unroll
            for (int cl = 0; cl < 2; cl++) {
                int o_sv = (c0 + cl) * 2;
                atomicAdd(&sst[o_sv],          r8[cl*4+0]);
                atomicAdd(&sst[32 + o_sv],     r8[cl*4+1]);
                atomicAdd(&sst[o_sv + 1],      r8[cl*4+2]);
                atomicAdd(&sst[32 + o_sv + 1], r8[cl*4+3]);
            }
        }
    }
    __syncthreads();   // all S reads done; sst atomics drained

    // stage results into S (32 x 49), then coalesced copy out
    #pragma unroll
    for (int cl = 0; cl < 2; cl++) {
        int c = c0 + cl;
        S[(c*2)*49 + i0 + 0]   = svv[cl][0];
        S[(c*2)*49 + i0 + 1]   = svv[cl][1];
        S[(c*2)*49 + i0 + 2]   = svv[cl][2];
        S[(c*2+1)*49 + i0 + 0] = sev[cl][0];
        S[(c*2+1)*49 + i0 + 1] = sev[cl][1];
        S[(c*2+1)*49 + i0 + 2] = sev[cl][2];
    }
    __syncthreads();
    {
        float* dst = d_outpre + (size_t)b * 12288 + g * 1536;
        #pragma unroll
        for (int t = 0; t < 12; t++) {
            int idx = t * 128 + tid;
            dst[idx] = S[(idx / 48) * 49 + idx % 48];
        }
        if (tid < 32) {
            atomicAdd(&d_osum[g * 32 + tid], sst[tid]);
            atomicAdd(&d_osq[g * 32 + tid],  sst[32 + tid]);
        }
    }
}

// ------- pass 4: out BN (inlined) + s-pair sum + transpose -----------------
__global__ void k_out(float* __restrict__ out,
                      const float* __restrict__ gout, const float* __restrict__ bout) {
    __shared__ float tile[48 * 49];
    int tid = threadIdx.x;
    int w = blockIdx.x % 48, gc = blockIdx.x / 48;
    int o0 = gc * 2, o1 = o0 + 1;
    float s0, sh0, s1, sh1;
    bn_params(d_osum[o0], d_osq[o0], 110592.f, gout[o0], bout[o0], s0, sh0);
    bn_params(d_osum[o1], d_osq[o1], 110592.f, gout[o1], bout[o1], s1, sh1);
    float sh = sh0 + sh1;
    #pragma unroll
    for (int t = 0; t < 9; t++) {
        int idx = t * 256 + tid;
        int d = idx / 48, h = idx % 48;
        int bb = w * 48 + d;
        float v = d_outpre[bb * 12288 + o0 * 48 + h] * s0
                + d_outpre[bb * 12288 + o1 * 48 + h] * s1 + sh;
        tile[h * 49 + d] = v;
    }
    __syncthreads();
    #pragma unroll
    for (int t = 0; t < 9; t++) {
        int idx = t * 256 + tid;
        int h = idx / 48, d = idx % 48;
        out[gc * NHWD + h * 2304 + w * 48 + d] = tile[h * 49 + d];
    }
}

// ---------------------------------------------------------------------------
extern "C" void kernel_launch(void* const* d_in, const int* in_sizes, int n_in,
                              void* d_out, int out_size) {
    const float* x    = (const float*)d_in[0];
    const float* Wkv  = (const float*)d_in[1];
    const float* Wq   = (const float*)d_in[2];
    const float* gkv  = (const float*)d_in[3];
    const float* bkv  = (const float*)d_in[4];
    const float* gq   = (const float*)d_in[5];
    const float* bq   = (const float*)d_in[6];
    const float* gsim = (const float*)d_in[7];
    const float* bsim = (const float*)d_in[8];   // shift dropped (softmax invariant)
    const float* gout = (const float*)d_in[9];
    const float* bout = (const float*)d_in[10];
    const float* rel  = (const float*)d_in[11];
    const float* fqr  = (const float*)d_in[12];
    const float* fkr  = (const float*)d_in[13];
    const float* fsv  = (const float*)d_in[14];
    const float* fsve = (const float*)d_in[15];
    (void)bsim;
    float* out = (float*)d_out;

    const int proj_smem = (256 * 65 + 64 * 64) * (int)sizeof(float);
    cudaFuncSetAttribute(k_proj, cudaFuncAttributeMaxDynamicSharedMemorySize, proj_smem);

    k_pre<<<4, 256>>>(rel);
    k_proj<<<1728, 256, proj_smem>>>(x, Wkv, Wq);
    k_simstat2<<<2304, 256>>>(fqr, fkr, gkv, bkv, gq, bq);
    k_attn<<<18432, 128>>>(rel, fqr, fkr, fsv, fsve, gkv, bkv, gq, bq, gsim);
    k_out<<<6144, 256>>>(out, gout, bout);
}

// round 8
// speedup vs baseline: 2.0043x; 1.2741x over previous
#include <cuda_runtime.h>
#include <math.h>

#define H48   48
#define NG    8
#define NC    64
#define NB    2304
#define NHWD  110592
#define NOC   256
#define EPSV  1e-5f

// ---------------- scratch ----------------
__device__ float d_proj[NOC * NHWD];        // [o][b*48 + h]
__device__ float d_outpre[NB * NOC * H48];  // [b][g*1536 + o_local*48 + i]
__device__ float d_psum[NOC], d_psq[NOC];
__device__ float d_ssum[24],  d_ssq[24];
__device__ float d_osum[NOC], d_osq[NOC];
__device__ float d_W1q[8 * 48], d_W1k[8 * 48];
__device__ float d_W2q[36 * 48], d_W2k[36 * 48];

__device__ __forceinline__ void decode_pair(int op, int& a, int& b) {
    a = 0; int r = op;
    while (r >= 7 - a) { r -= 7 - a; a++; }
    b = a + 1 + r;
}

// ------------- pass 0: zero accumulators + rel window tables --------------
__global__ void k_pre(const float* __restrict__ rel) {
    int tid = threadIdx.x;
    if (blockIdx.x == 0) {
        if (tid < NOC) { d_psum[tid] = 0.f; d_psq[tid] = 0.f; d_osum[tid] = 0.f; d_osq[tid] = 0.f; }
        if (tid < 24)  { d_ssum[tid] = 0.f; d_ssq[tid]  = 0.f; }
        for (int idx = tid; idx < 16 * 48; idx += 256) {
            int r = idx / 48, t = idx % 48;
            float s = 0.f;
            for (int d = 0; d < 48; d++) s += rel[r * 95 + t + d];
            if (r < 8) d_W1q[r * 48 + t] = s; else d_W1k[(r - 8) * 48 + t] = s;
        }
    } else {
        for (int idx = tid; idx < 24 * 48; idx += 256) {
            int u = (blockIdx.x - 1) * 24 + idx / 48, t = idx % 48;
            int side = u / 36, p = u % 36;
            int a, b; float f;
            if (p < 8) { a = p; b = p; f = 1.f; } else { decode_pair(p - 8, a, b); f = 2.f; }
            const float* ra = rel + (side * 8 + a) * 95;
            const float* rb = rel + (side * 8 + b) * 95;
            float s = 0.f;
            for (int d = 0; d < 48; d++) s = fmaf(ra[t + d], rb[t + d], s);
            s *= f;
            if (side == 0) d_W2q[p * 48 + t] = s; else d_W2k[p * 48 + t] = s;
        }
    }
}

// ---------------- pass 1: projection GEMM + per-channel stats --------------
__global__ void k_proj(const float* __restrict__ x,
                       const float* __restrict__ Wkv,
                       const float* __restrict__ Wq) {
    extern __shared__ float sm[];
    float* Ws = sm;              // 256 x 65
    float* Xs = sm + 256 * 65;   // 64 x 64
    int tid = threadIdx.x;
    int bt = blockIdx.x % 288, ht = blockIdx.x / 288;
    int b0 = bt * 8, h0 = ht * 8;

    for (int idx = tid; idx < 256 * 64; idx += 256) {
        int o = idx >> 6, c = idx & 63;
        Ws[o * 65 + c] = (o < 192) ? Wkv[o * 64 + c] : Wq[(o - 192) * 64 + c];
    }
    #pragma unroll
    for (int t = 0; t < 16; t++) {
        int idx = t * 256 + tid;
        int c = idx >> 6, sp = idx & 63;
        int hl = sp >> 3, bl = sp & 7;
        Xs[c * 64 + sp] = x[c * NHWD + (h0 + hl) * 2304 + b0 + bl];
    }
    __syncthreads();

    int og = tid >> 3, bl = tid & 7;
    float acc[8][8];
    #pragma unroll
    for (int i = 0; i < 8; i++)
        #pragma unroll
        for (int h = 0; h < 8; h++) acc[i][h] = 0.f;

    #pragma unroll 4
    for (int c = 0; c < 64; c++) {
        float xv[8];
        #pragma unroll
        for (int hl = 0; hl < 8; hl++) xv[hl] = Xs[c * 64 + hl * 8 + bl];
        #pragma unroll
        for (int i = 0; i < 8; i++) {
            float wv = Ws[(og * 8 + i) * 65 + c];
            #pragma unroll
            for (int hl = 0; hl < 8; hl++) acc[i][hl] = fmaf(wv, xv[hl], acc[i][hl]);
        }
    }

    #pragma unroll
    for (int i = 0; i < 8; i++) {
        int o = og * 8 + i;
        float s = 0.f, q = 0.f;
        #pragma unroll
        for (int hl = 0; hl < 8; hl++) { float v = acc[i][hl]; s += v; q += v * v; }
        float* base = d_proj + o * NHWD + (b0 + bl) * 48 + h0;
        *(float4*)(base)     = make_float4(acc[i][0], acc[i][1], acc[i][2], acc[i][3]);
        *(float4*)(base + 4) = make_float4(acc[i][4], acc[i][5], acc[i][6], acc[i][7]);
        s += __shfl_down_sync(0xffffffffu, s, 4, 8);
        s += __shfl_down_sync(0xffffffffu, s, 2, 8);
        s += __shfl_down_sync(0xffffffffu, s, 1, 8);
        q += __shfl_down_sync(0xffffffffu, q, 4, 8);
        q += __shfl_down_sync(0xffffffffu, q, 2, 8);
        q += __shfl_down_sync(0xffffffffu, q, 1, 8);
        if (bl == 0) { atomicAdd(&d_psum[o], s); atomicAdd(&d_psq[o], q); }
    }
}

__device__ __forceinline__ void bn_params(float sum, float sq, float n, float gamma, float beta,
                                          float& sc, float& sh) {
    float m = sum / n;
    float var = sq / n - m * m;
    sc = rsqrtf(var + EPSV) * gamma;
    sh = beta - m * sc;
}

// ------------- pass 2: sim BN stats via Gram factorization -----------------
__global__ __launch_bounds__(256) void k_simstat2(const float* __restrict__ fqr_p,
                                                  const float* __restrict__ fkr_p,
                                                  const float* __restrict__ gkv, const float* __restrict__ bkv,
                                                  const float* __restrict__ gq,  const float* __restrict__ bq) {
    __shared__ float qs[64 * 49], ks[64 * 49];
    __shared__ float sW2q[36 * 49], sW2k[36 * 49];
    __shared__ float sW1q[8 * 48], sW1k[8 * 48];
    __shared__ float qsc[64], qsh[64], ksc[64], ksh[64];
    int tid = threadIdx.x;
    int b = blockIdx.x;
    int g = tid >> 5, lane = tid & 31;

    if (tid < 64) {
        int oq = 192 + tid;
        bn_params(d_psum[oq], d_psq[oq], 110592.f, gq[tid], bq[tid], qsc[tid], qsh[tid]);
        int ok = (tid >> 3) * 24 + (tid & 7);
        bn_params(d_psum[ok], d_psq[ok], 110592.f, gkv[ok], bkv[ok], ksc[tid], ksh[tid]);
    }
    __syncthreads();

    for (int idx = tid; idx < 64 * 48; idx += 256) {
        int c64 = idx / 48, h = idx % 48;
        int oq = 192 + c64;
        qs[c64 * 49 + h] = d_proj[oq * NHWD + b * 48 + h] * qsc[c64] + qsh[c64];
        int ok = (c64 >> 3) * 24 + (c64 & 7);
        ks[c64 * 49 + h] = d_proj[ok * NHWD + b * 48 + h] * ksc[c64] + ksh[c64];
    }
    for (int idx = tid; idx < 36 * 48; idx += 256) {
        int p = idx / 48, t = idx % 48;
        sW2q[p * 49 + t] = d_W2q[idx];
        sW2k[p * 49 + t] = d_W2k[idx];
    }
    for (int idx = tid; idx < 8 * 48; idx += 256) { sW1q[idx] = d_W1q[idx]; sW1k[idx] = d_W1k[idx]; }
    __syncthreads();

    float vsumqk = 0.f, vsqqk = 0.f, vtq = 0.f, vtk = 0.f, vsumqr = 0.f, vsumkr = 0.f;

    if (lane < 28) {
        int a, bb2; decode_pair(lane, a, bb2);
        const float* qa = &qs[(g * 8 + a) * 49];
        const float* qb = &qs[(g * 8 + bb2) * 49];
        const float* ka = &ks[(g * 8 + a) * 49];
        const float* kb = &ks[(g * 8 + bb2) * 49];
        const float* w2q = &sW2q[(8 + lane) * 49];
        const float* w2k = &sW2k[(8 + lane) * 49];
        float Qp = 0.f, Kp = 0.f, tq = 0.f, tk = 0.f;
        #pragma unroll 8
        for (int i = 0; i < 48; i++) {
            float qq = qa[i] * qb[i]; Qp += qq; tq = fmaf(qq, w2q[i], tq);
            float kk = ka[i] * kb[i]; Kp += kk; tk = fmaf(kk, w2k[i], tk);
        }
        vsqqk = 2.f * Qp * Kp;
        vtq = tq; vtk = tk;
    }
    if (lane < 8) {
        const float* qc = &qs[(g * 8 + lane) * 49];
        const float* kc = &ks[(g * 8 + lane) * 49];
        const float* w2q = &sW2q[lane * 49];
        const float* w2k = &sW2k[lane * 49];
        const float* w1q = &sW1q[lane * 48];
        const float* w1k = &sW1k[lane * 48];
        float Sq = 0.f, Sk = 0.f, Qd = 0.f, Kd = 0.f, tqd = 0.f, tkd = 0.f, sqr = 0.f, skr = 0.f;
        #pragma unroll 8
        for (int i = 0; i < 48; i++) {
            float qv = qc[i], kv = kc[i];
            Sq += qv; Sk += kv;
            float q2 = qv * qv, k2 = kv * kv;
            Qd += q2; Kd += k2;
            tqd = fmaf(q2, w2q[i], tqd);
            tkd = fmaf(k2, w2k[i], tkd);
            sqr = fmaf(qv, w1q[i], sqr);
            skr = fmaf(kv, w1k[i], skr);
        }
        vsumqk = Sq * Sk;
        vsqqk += Qd * Kd;
        vtq += tqd; vtk += tkd;
        vsumqr = sqr; vsumkr = skr;
    }
    #pragma unroll
    for (int off = 16; off; off >>= 1) {
        vsumqk += __shfl_xor_sync(0xffffffffu, vsumqk, off);
        vsqqk  += __shfl_xor_sync(0xffffffffu, vsqqk,  off);
        vtq    += __shfl_xor_sync(0xffffffffu, vtq,    off);
        vtk    += __shfl_xor_sync(0xffffffffu, vtk,    off);
        vsumqr += __shfl_xor_sync(0xffffffffu, vsumqr, off);
        vsumkr += __shfl_xor_sync(0xffffffffu, vsumkr, off);
    }
    if (lane == 0) {
        float fqr = fqr_p[0], fkr = fkr_p[0];
        atomicAdd(&d_ssum[g], vsumqk);
        atomicAdd(&d_ssq[g],  vsqqk);
        atomicAdd(&d_ssum[8 + g], fqr * vsumqr);
        atomicAdd(&d_ssq[8 + g],  fqr * fqr * vtq);
        atomicAdd(&d_ssum[16 + g], fkr * vsumkr);
        atomicAdd(&d_ssq[16 + g],  fkr * fkr * vtk);
    }
}

// ------- pass 3: logits + softmax + sv/sve (bank-conflict-free strides) ----
// smem (floats):
//   S    [0, 2304)      logits (stride 48); later 32x49 staging
//   sq   [2304, 2688)   8x48 BN'd q
//   sk   [2688, 3072)   8x48 BN'd k
//   D    [3072, 5488)   2416:
//        Phase A: srq = D+0 (8 x stride96, cb-scaled), srk = D+768 (8 x stride96)
//        Phase C: svs = D+0 (16 x stride50, fsv-scaled)
//                 sveS = D+800 (16 x stride101, fsve-scaled, +1 offset)
//   sst  [5488, 5552)
//   psc  [5552, 5584)  psh [5584, 5616)
__global__ __launch_bounds__(128, 8) void k_attn(const float* __restrict__ rel,
                       const float* __restrict__ fqr_p, const float* __restrict__ fkr_p,
                       const float* __restrict__ fsv_p, const float* __restrict__ fsve_p,
                       const float* __restrict__ gkv, const float* __restrict__ bkv,
                       const float* __restrict__ gq,  const float* __restrict__ bq,
                       const float* __restrict__ gsim) {
    __shared__ __align__(16) float sm[5616];
    float* S   = sm;
    float* sq  = sm + 2304;
    float* sk  = sm + 2688;
    float* D   = sm + 3072;
    float* sst = sm + 5488;
    float* psc = sm + 5552;
    float* psh = sm + 5584;

    int tid = threadIdx.x;
    int b = blockIdx.x >> 3, g = blockIdx.x & 7;
    if (tid < 64) sst[tid] = 0.f;

    float fqr = fqr_p[0], fkr = fkr_p[0], fsv = fsv_p[0], fsve = fsve_p[0];

    float ca, cb, cc2;
    {
        float n2 = 5308416.f, m, v;
        m = d_ssum[g] / n2;      v = d_ssq[g] / n2 - m * m;      ca  = rsqrtf(v + EPSV) * gsim[g];
        m = d_ssum[8 + g] / n2;  v = d_ssq[8 + g] / n2 - m * m;  cb  = rsqrtf(v + EPSV) * gsim[8 + g]  * fqr;
        m = d_ssum[16 + g] / n2; v = d_ssq[16 + g] / n2 - m * m; cc2 = rsqrtf(v + EPSV) * gsim[16 + g] * fkr;
    }
    if (tid < 32) {
        int o; float gamma, beta;
        if (tid < 8)       { o = 192 + g * 8 + tid;       gamma = gq[o - 192];  beta = bq[o - 192]; }
        else if (tid < 16) { o = g * 24 + (tid - 8);      gamma = gkv[o];       beta = bkv[o]; }
        else               { o = g * 24 + 8 + (tid - 16); gamma = gkv[o];       beta = bkv[o]; }
        bn_params(d_psum[o], d_psq[o], 110592.f, gamma, beta, psc[tid], psh[tid]);
    }
    __syncthreads();

    for (int idx = tid; idx < 384; idx += 128) {
        int c = idx / 48, h = idx % 48;
        sq[idx] = d_proj[(192 + g * 8 + c) * NHWD + b * 48 + h] * psc[c] + psh[c];
        sk[idx] = d_proj[(g * 24 + c) * NHWD + b * 48 + h] * psc[8 + c] + psh[8 + c];
    }
    for (int idx = tid; idx < 16 * 95; idx += 128) {
        int r = idx / 95, d = idx % 95;
        float v = rel[idx];
        if (r < 8) D[r * 96 + d]         = cb  * v;     // srq
        else       D[768 + (r-8)*96 + d] = cc2 * v;     // srk
    }
    __syncthreads();

    int c0 = (tid & 7) * 2, i0 = (tid >> 3) * 3;
    int j0 = (tid & 7) * 6;

    // Phase A: fused logits
    {
        float L[18];
        #pragma unroll
        for (int e = 0; e < 18; e++) L[e] = 0.f;
        #pragma unroll
        for (int c = 0; c < 8; c++) {
            float qr[3], qa[3], kv[6], rqv[8], rkv[8];
            #pragma unroll
            for (int di = 0; di < 3; di++) { qr[di] = sq[c * 48 + i0 + di]; qa[di] = ca * qr[di]; }
            float2 kv01 = *(const float2*)(sk + c * 48 + j0);
            float2 kv23 = *(const float2*)(sk + c * 48 + j0 + 2);
            float2 kv45 = *(const float2*)(sk + c * 48 + j0 + 4);
            kv[0] = kv01.x; kv[1] = kv01.y; kv[2] = kv23.x;
            kv[3] = kv23.y; kv[4] = kv45.x; kv[5] = kv45.y;
            const float* rqp = D + c * 96 + (i0 - j0 + 42);
            const float* rkp = D + 768 + c * 96 + (j0 - i0 + 45);
            #pragma unroll
            for (int t = 0; t < 8; t++) { rqv[t] = rqp[t]; rkv[t] = rkp[t]; }
            #pragma unroll
            for (int di = 0; di < 3; di++)
                #pragma unroll
                for (int dj = 0; dj < 6; dj++) {
                    int e = di * 6 + dj;
                    L[e] = fmaf(kv[dj], qa[di],            L[e]);
                    L[e] = fmaf(kv[dj], rkv[dj + 2 - di],  L[e]);
                    L[e] = fmaf(qr[di], rqv[di + 5 - dj],  L[e]);
                }
        }
        #pragma unroll
        for (int di = 0; di < 3; di++)
            #pragma unroll
            for (int dj = 0; dj < 6; dj++)
                S[(i0 + di) * 48 + (j0 + dj)] = L[di * 6 + dj];
    }
    __syncthreads();   // Phase A done: S valid, D free

    // overwrite D with Phase C data (hidden behind softmax)
    for (int idx = tid; idx < 768; idx += 128) {
        int c = idx / 48, h = idx % 48;
        D[c * 50 + h] = fsv * (d_proj[(g * 24 + 8 + c) * NHWD + b * 48 + h] * psc[16 + c] + psh[16 + c]);
    }
    for (int idx = tid; idx < 16 * 95; idx += 128) {
        int r = idx / 95, d = idx % 95;
        D[800 + r * 101 + d + 1] = fsve * rel[(16 + r) * 95 + d];
    }

    // Phase B: softmax, one row per 16-lane half-warp
    {
        int w = tid >> 5, hw = (tid >> 4) & 1, hl = tid & 15;
        for (int t = 0; t < 6; t++) {
            int r = w * 12 + t * 2 + hw;
            float a = S[r * 48 + hl];
            float b2 = S[r * 48 + 16 + hl];
            float c3 = S[r * 48 + 32 + hl];
            float m = fmaxf(a, fmaxf(b2, c3));
            #pragma unroll
            for (int off = 8; off; off >>= 1) m = fmaxf(m, __shfl_xor_sync(0xffffffffu, m, off));
            float ea = __expf(a - m), eb = __expf(b2 - m), ec = __expf(c3 - m);
            float s = ea + eb + ec;
            #pragma unroll
            for (int off = 8; off; off >>= 1) s += __shfl_xor_sync(0xffffffffu, s, off);
            float inv = 1.f / s;
            S[r * 48 + hl]      = ea * inv;
            S[r * 48 + 16 + hl] = eb * inv;
            S[r * 48 + 32 + hl] = ec * inv;
        }
    }
    __syncthreads();

    // Phase C: sv + sve; conflict-free float2 v reads (stride 50), ve stride 101
    float svv[2][3] = {{0.f,0.f,0.f},{0.f,0.f,0.f}};
    float sev[2][3] = {{0.f,0.f,0.f},{0.f,0.f,0.f}};
    {
        const float* Sr0 = &S[i0 * 48];
        const float* Sr1 = &S[(i0 + 1) * 48];
        const float* Sr2 = &S[(i0 + 2) * 48];
        const float* vp0 = D + c0 * 50;
        const float* vp1 = D + (c0 + 1) * 50;
        const float* ve0 = D + 800 + c0 * 101 + 1;
        const float* ve1 = D + 800 + (c0 + 1) * 101 + 1;
        float wa0 = ve0[i0 + 47], wa1 = ve0[i0 + 48], wa2 = ve0[i0 + 49];
        float wb0 = ve1[i0 + 47], wb1 = ve1[i0 + 48], wb2 = ve1[i0 + 49];
        #pragma unroll
        for (int jo = 0; jo < 12; jo++) {
            float4 s0q = *(const float4*)(Sr0 + jo * 4);
            float4 s1q = *(const float4*)(Sr1 + jo * 4);
            float4 s2q = *(const float4*)(Sr2 + jo * 4);
            float2 vaA = *(const float2*)(vp0 + jo * 4);
            float2 vaB = *(const float2*)(vp0 + jo * 4 + 2);
            float2 vbA = *(const float2*)(vp1 + jo * 4);
            float2 vbB = *(const float2*)(vp1 + jo * 4 + 2);
            float va4[4] = {vaA.x, vaA.y, vaB.x, vaB.y};
            float vb4[4] = {vbA.x, vbA.y, vbB.x, vbB.y};
            #pragma unroll
            for (int jj = 0; jj < 4; jj++) {
                int j = jo * 4 + jj;
                float sa = (jj == 0) ? s0q.x : (jj == 1) ? s0q.y : (jj == 2) ? s0q.z : s0q.w;
                float sb = (jj == 0) ? s1q.x : (jj == 1) ? s1q.y : (jj == 2) ? s1q.z : s1q.w;
                float sc = (jj == 0) ? s2q.x : (jj == 1) ? s2q.y : (jj == 2) ? s2q.z : s2q.w;
                float va = va4[jj], vb = vb4[jj];
                svv[0][0] = fmaf(sa, va, svv[0][0]);
                svv[0][1] = fmaf(sb, va, svv[0][1]);
                svv[0][2] = fmaf(sc, va, svv[0][2]);
                svv[1][0] = fmaf(sa, vb, svv[1][0]);
                svv[1][1] = fmaf(sb, vb, svv[1][1]);
                svv[1][2] = fmaf(sc, vb, svv[1][2]);
                sev[0][0] = fmaf(sa, wa0, sev[0][0]);
                sev[0][1] = fmaf(sb, wa1, sev[0][1]);
                sev[0][2] = fmaf(sc, wa2, sev[0][2]);
                sev[1][0] = fmaf(sa, wb0, sev[1][0]);
                sev[1][1] = fmaf(sb, wb1, sev[1][1]);
                sev[1][2] = fmaf(sc, wb2, sev[1][2]);
                wa2 = wa1; wa1 = wa0; wa0 = ve0[i0 + 46 - j];
                wb2 = wb1; wb1 = wb0; wb0 = ve1[i0 + 46 - j];
            }
        }
    }

    // out-BN stats: register reduce across threads sharing c0
    {
        float r8[8];
        #pragma unroll
        for (int cl = 0; cl < 2; cl++) {
            float s1 = svv[cl][0] + svv[cl][1] + svv[cl][2];
            float q1 = svv[cl][0]*svv[cl][0] + svv[cl][1]*svv[cl][1] + svv[cl][2]*svv[cl][2];
            float s2 = sev[cl][0] + sev[cl][1] + sev[cl][2];
            float q2 = sev[cl][0]*sev[cl][0] + sev[cl][1]*sev[cl][1] + sev[cl][2]*sev[cl][2];
            r8[cl*4+0] = s1; r8[cl*4+1] = q1; r8[cl*4+2] = s2; r8[cl*4+3] = q2;
        }
        #pragma unroll
        for (int k = 0; k < 8; k++) {
            r8[k] += __shfl_xor_sync(0xffffffffu, r8[k], 8);
            r8[k] += __shfl_xor_sync(0xffffffffu, r8[k], 16);
        }
        if ((tid & 31) < 8) {
            #pragma unroll
            for (int cl = 0; cl < 2; cl++) {
                int o_sv = (c0 + cl) * 2;
                atomicAdd(&sst[o_sv],          r8[cl*4+0]);
                atomicAdd(&sst[32 + o_sv],     r8[cl*4+1]);
                atomicAdd(&sst[o_sv + 1],      r8[cl*4+2]);
                atomicAdd(&sst[32 + o_sv + 1], r8[cl*4+3]);
            }
        }
    }
    __syncthreads();

    // stage into S (32 x 49), then coalesced copy out
    #pragma unroll
    for (int cl = 0; cl < 2; cl++) {
        int c = c0 + cl;
        S[(c*2)*49 + i0 + 0]   = svv[cl][0];
        S[(c*2)*49 + i0 + 1]   = svv[cl][1];
        S[(c*2)*49 + i0 + 2]   = svv[cl][2];
        S[(c*2+1)*49 + i0 + 0] = sev[cl][0];
        S[(c*2+1)*49 + i0 + 1] = sev[cl][1];
        S[(c*2+1)*49 + i0 + 2] = sev[cl][2];
    }
    __syncthreads();
    {
        float* dst = d_outpre + (size_t)b * 12288 + g * 1536;
        #pragma unroll
        for (int t = 0; t < 12; t++) {
            int idx = t * 128 + tid;
            dst[idx] = S[(idx / 48) * 49 + idx % 48];
        }
        if (tid < 32) {
            atomicAdd(&d_osum[g * 32 + tid], sst[tid]);
            atomicAdd(&d_osq[g * 32 + tid],  sst[32 + tid]);
        }
    }
}

// ------- pass 4: out BN (inlined) + s-pair sum + transpose -----------------
__global__ void k_out(float* __restrict__ out,
                      const float* __restrict__ gout, const float* __restrict__ bout) {
    __shared__ float tile[48 * 49];
    int tid = threadIdx.x;
    int w = blockIdx.x % 48, gc = blockIdx.x / 48;
    int o0 = gc * 2, o1 = o0 + 1;
    float s0, sh0, s1, sh1;
    bn_params(d_osum[o0], d_osq[o0], 110592.f, gout[o0], bout[o0], s0, sh0);
    bn_params(d_osum[o1], d_osq[o1], 110592.f, gout[o1], bout[o1], s1, sh1);
    float sh = sh0 + sh1;
    #pragma unroll
    for (int t = 0; t < 9; t++) {
        int idx = t * 256 + tid;
        int d = idx / 48, h = idx % 48;
        int bb = w * 48 + d;
        float v = d_outpre[bb * 12288 + o0 * 48 + h] * s0
                + d_outpre[bb * 12288 + o1 * 48 + h] * s1 + sh;
        tile[h * 49 + d] = v;
    }
    __syncthreads();
    #pragma unroll
    for (int t = 0; t < 9; t++) {
        int idx = t * 256 + tid;
        int h = idx / 48, d = idx % 48;
        out[gc * NHWD + h * 2304 + w * 48 + d] = tile[h * 49 + d];
    }
}

// ---------------------------------------------------------------------------
extern "C" void kernel_launch(void* const* d_in, const int* in_sizes, int n_in,
                              void* d_out, int out_size) {
    const float* x    = (const float*)d_in[0];
    const float* Wkv  = (const float*)d_in[1];
    const float* Wq   = (const float*)d_in[2];
    const float* gkv  = (const float*)d_in[3];
    const float* bkv  = (const float*)d_in[4];
    const float* gq   = (const float*)d_in[5];
    const float* bq   = (const float*)d_in[6];
    const float* gsim = (const float*)d_in[7];
    const float* bsim = (const float*)d_in[8];   // shift dropped (softmax invariant)
    const float* gout = (const float*)d_in[9];
    const float* bout = (const float*)d_in[10];
    const float* rel  = (const float*)d_in[11];
    const float* fqr  = (const float*)d_in[12];
    const float* fkr  = (const float*)d_in[13];
    const float* fsv  = (const float*)d_in[14];
    const float* fsve = (const float*)d_in[15];
    (void)bsim;
    float* out = (float*)d_out;

    const int proj_smem = (256 * 65 + 64 * 64) * (int)sizeof(float);
    cudaFuncSetAttribute(k_proj, cudaFuncAttributeMaxDynamicSharedMemorySize, proj_smem);

    k_pre<<<4, 256>>>(rel);
    k_proj<<<1728, 256, proj_smem>>>(x, Wkv, Wq);
    k_simstat2<<<2304, 256>>>(fqr, fkr, gkv, bkv, gq, bq);
    k_attn<<<18432, 128>>>(rel, fqr, fkr, fsv, fsve, gkv, bkv, gq, bq, gsim);
    k_out<<<6144, 256>>>(out, gout, bout);
}